// round 8
// baseline (speedup 1.0000x reference)
#include <cuda_runtime.h>
#include <cuda_fp16.h>
#include <cstdint>

#define F_DIM   128
#define FM_DIM  16
#define DIN     257
#define DH      514
#define UIN     144
#define UH      256
#define HID     128
#define T_OUT   12
#define SP      520     // padded row stride for Pd/Ps in HALVES (1040B, 16B-aligned)

#define MAXN 50048
#define MAXE 800000
#define MAXG 1024

// ---------------- scratch (no allocations allowed) ----------------
__device__ __align__(256) float  g_h0[MAXN * F_DIM];
__device__ __align__(256) float  g_h1[MAXN * F_DIM];
__device__ __align__(256) float  g_en2[MAXE];      // norm2, dst-sorted order
__device__ __align__(256) float  g_agg[MAXN * FM_DIM];
__device__ __align__(256) float  g_pooled[MAXG * HID];
__device__ __align__(256) __half g_Pd[MAXN * SP];  // h @ W1[0:128] + b1   (fp16)
__device__ __align__(256) __half g_Ps[MAXN * SP];  // h @ W1[128:256]      (fp16)
__device__ __align__(256) int    g_cur[MAXN];      // scan cursor
__device__ __align__(256) int    g_es[MAXE];       // sorted src
__device__ __align__(256) int    g_ed[MAXE];       // sorted dst

// ---------------- helpers ----------------
__device__ __forceinline__ float swishf(float x) {
    return __fdividef(x, 1.0f + __expf(-x));
}

typedef unsigned long long ull;

__device__ __forceinline__ void fma2(ull& d, ull a, ull b) {
    asm("fma.rn.f32x2 %0, %1, %2, %0;" : "+l"(d) : "l"(a), "l"(b));
}
__device__ __forceinline__ ull pack2(float x) {
    ull r;
    asm("mov.b64 %0, {%1, %1};" : "=l"(r) : "f"(x));
    return r;
}
__device__ __forceinline__ void unpack2(ull v, float& lo, float& hi) {
    asm("mov.b64 {%0, %1}, %2;" : "=f"(lo), "=f"(hi) : "l"(v));
}
// 4 packed halves -> float4
__device__ __forceinline__ float4 h4f4(uint2 v) {
    __half2 h0 = *(__half2*)&v.x;
    __half2 h1 = *(__half2*)&v.y;
    float2 f0 = __half22float2(h0);
    float2 f1 = __half22float2(h1);
    return make_float4(f0.x, f0.y, f1.x, f1.y);
}

// ---------------- small kernels ----------------
__global__ void zero_kernel(float* p, int n) {
    int i = blockIdx.x * blockDim.x + threadIdx.x;
    if (i < n) p[i] = 0.0f;
}
__global__ void izero_kernel(int* p, int n) {
    int i = blockIdx.x * blockDim.x + threadIdx.x;
    if (i < n) p[i] = 0;
}

__global__ void init_h_kernel(const void* zptr, const float* __restrict__ emb,
                              float* __restrict__ h, int N) {
    int i = blockIdx.x * blockDim.x + threadIdx.x;
    if (i >= N * F_DIM) return;
    int node = i / F_DIM, f = i % F_DIM;
    const int* z32 = (const int*)zptr;
    bool is64 = (z32[1] == 0) && (z32[3] == 0) && (z32[5] == 0);
    long long zv = is64 ? ((const long long*)zptr)[node] : (long long)z32[node];
    int e = (zv == 1) ? 0 : (int)(zv - 5);
    h[i] = emb[e * F_DIM + f];
}

// ---------------- counting sort of edges by dst ----------------
__global__ void hist_kernel(const int* __restrict__ ei, int* __restrict__ cnt, int E) {
    int e = blockIdx.x * blockDim.x + threadIdx.x;
    if (e < E) atomicAdd(&cnt[ei[E + e]], 1);
}

__global__ void scan_kernel(int* __restrict__ cnt, int* __restrict__ cur, int N) {
    __shared__ int sdata[1024];
    __shared__ int carry_s;
    if (threadIdx.x == 0) carry_s = 0;
    __syncthreads();
    for (int base = 0; base < N; base += 1024) {
        int i = base + threadIdx.x;
        int v = (i < N) ? cnt[i] : 0;
        sdata[threadIdx.x] = v;
        __syncthreads();
        for (int ofs = 1; ofs < 1024; ofs <<= 1) {
            int t = (threadIdx.x >= ofs) ? sdata[threadIdx.x - ofs] : 0;
            __syncthreads();
            sdata[threadIdx.x] += t;
            __syncthreads();
        }
        int excl = sdata[threadIdx.x] - v + carry_s;
        if (i < N) cur[i] = excl;
        __syncthreads();
        if (threadIdx.x == 0) carry_s += sdata[1023];
        __syncthreads();
    }
}

__global__ void scatter_kernel(const int* __restrict__ ei, const float* __restrict__ pos,
                               int* __restrict__ cur,
                               int* __restrict__ es, int* __restrict__ ed,
                               float* __restrict__ en2, int E) {
    int e = blockIdx.x * blockDim.x + threadIdx.x;
    if (e >= E) return;
    int s = ei[e], d = ei[E + e];
    float dx = pos[s * 3 + 0] - pos[d * 3 + 0];
    float dy = pos[s * 3 + 1] - pos[d * 3 + 1];
    float dz = pos[s * 3 + 2] - pos[d * 3 + 2];
    int p = atomicAdd(&cur[d], 1);
    es[p] = s; ed[p] = d;
    en2[p] = dx * dx + dy * dy + dz * dz;
}

// ---------------- per-node pre-GEMM: P = h @ W (+bias), fp16 out ----------
#define PREP_SMEM_BYTES ((64 * 132 + 8 * 132) * 4)

__global__ __launch_bounds__(256)
void prep_gemm_kernel(const float* __restrict__ h, const float* __restrict__ W1,
                      const float* __restrict__ bias,
                      __half* __restrict__ Pd, __half* __restrict__ Ps, int N) {
    extern __shared__ float sm[];
    float* sH = sm;             // 64 x 132
    float* sB = sH + 64 * 132;  // 8 x 132

    const int tid = threadIdx.x;
    const int n0 = blockIdx.x * 64;
    const int c0 = blockIdx.y * 128;
    const int which = blockIdx.z;
    const float* W = W1 + (size_t)which * 128 * DH;
    __half* P = which ? Ps : Pd;

    for (int idx = tid; idx < 64 * 128; idx += 256) {
        int r = idx >> 7, c = idx & 127;
        int node = n0 + r;
        sH[r * 132 + c] = (node < N) ? h[(size_t)node * F_DIM + c] : 0.0f;
    }
    __syncthreads();

    const int ty = tid >> 4, tx = tid & 15;
    const int r0 = ty * 4, ct = tx * 8;

    ull C01[4], C23[4], C45[4], C67[4];
    #pragma unroll
    for (int i = 0; i < 4; i++) { C01[i] = 0; C23[i] = 0; C45[i] = 0; C67[i] = 0; }

    for (int k0 = 0; k0 < 128; k0 += 8) {
        #pragma unroll
        for (int it = 0; it < 4; it++) {
            int t = tid + it * 256;
            int kk = t >> 7, c = t & 127;
            int col = c0 + c;
            sB[kk * 132 + c] = (col < DH) ? W[(size_t)(k0 + kk) * DH + col] : 0.0f;
        }
        __syncthreads();
        #pragma unroll
        for (int kk = 0; kk < 8; kk++) {
            const float* bp = sB + kk * 132 + ct;
            ull b01 = *(const ull*)(bp);
            ull b23 = *(const ull*)(bp + 2);
            ull b45 = *(const ull*)(bp + 4);
            ull b67 = *(const ull*)(bp + 6);
            #pragma unroll
            for (int i = 0; i < 4; i++) {
                ull aa = pack2(sH[(r0 + i) * 132 + k0 + kk]);
                fma2(C01[i], aa, b01); fma2(C23[i], aa, b23);
                fma2(C45[i], aa, b45); fma2(C67[i], aa, b67);
            }
        }
        __syncthreads();
    }

    #pragma unroll
    for (int i = 0; i < 4; i++) {
        int node = n0 + r0 + i;
        if (node >= N) continue;
        float v[8];
        unpack2(C01[i], v[0], v[1]); unpack2(C23[i], v[2], v[3]);
        unpack2(C45[i], v[4], v[5]); unpack2(C67[i], v[6], v[7]);
        int col0 = c0 + ct;
        __half* prow = P + (size_t)node * SP + col0;
        #pragma unroll
        for (int j = 0; j < 8; j++)
            v[j] += (which == 0 && col0 + j < DH) ? bias[col0 + j] : 0.0f;
        if (col0 + 8 <= DH) {
            __half2 h01 = __floats2half2_rn(v[0], v[1]);
            __half2 h23 = __floats2half2_rn(v[2], v[3]);
            __half2 h45 = __floats2half2_rn(v[4], v[5]);
            __half2 h67 = __floats2half2_rn(v[6], v[7]);
            uint4 st;
            st.x = *(unsigned*)&h01; st.y = *(unsigned*)&h23;
            st.z = *(unsigned*)&h45; st.w = *(unsigned*)&h67;
            *(uint4*)prow = st;
        } else {
            #pragma unroll
            for (int j = 0; j < 8; j++)
                if (col0 + j < SP)
                    prow[j] = __float2half_rn((col0 + j < DH) ? v[j] : 0.0f);
        }
    }
}

// ---------------- edge phase: warp-autonomous, dst-sorted, fp16 gather ----
// 8 warps/block, each warp owns 8 edges end-to-end. Lane -> (edge el=lane>>2,
// quarter part/cb=lane&3). Per 64-k tile: gather uint4 -> swish -> private
// per-warp sA slice (syncwarp only) -> mini-GEMM into per-lane 4-col accums.
#define EPB 64
#define SAE 68
#define EDGE_SMEM_FLOATS (516 * 16 + 516 + EPB * SAE)
#define EDGE_SMEM_BYTES  (EDGE_SMEM_FLOATS * 4 + EPB * 4 * 4)

__global__ __launch_bounds__(256)
void edge_kernel(const __half* __restrict__ Pd, const __half* __restrict__ Ps,
                 const float* __restrict__ Wn,   // W1 row 256 (norm2 row)
                 const float* __restrict__ W2, const float* __restrict__ b2,
                 const int* __restrict__ es, const int* __restrict__ ed,
                 const float* __restrict__ en2,
                 float* __restrict__ agg, int E) {
    extern __shared__ float sm[];
    float* sW2 = sm;                 // 516 x 16 (rows >=514 zero)
    float* sWn = sW2 + 516 * 16;     // 516 (pad zero)
    float* sA  = sWn + 516;          // 64 x 68 (8 per warp, private slices)
    int*   sDst = (int*)(sA + EPB * SAE);
    int*   sDc  = sDst + EPB;
    int*   sSc  = sDc + EPB;
    float* sN2  = (float*)(sSc + EPB);

    const int tid = threadIdx.x;
    const int e0 = blockIdx.x * EPB;

    for (int i = tid; i < 516 * 16; i += 256) {
        int k = i >> 4;
        sW2[i] = (k < DH) ? W2[i] : 0.0f;
    }
    for (int i = tid; i < 516; i += 256)
        sWn[i] = (i < DH) ? Wn[i] : 0.0f;
    if (tid < EPB) {
        int e = e0 + tid;
        if (e < E) {
            sDst[tid] = ed[e]; sDc[tid] = ed[e]; sSc[tid] = es[e];
            sN2[tid] = en2[e];
        } else {
            sDst[tid] = -1; sDc[tid] = 0; sSc[tid] = 0; sN2[tid] = 0.0f;
        }
    }
    __syncthreads();

    const int warp = tid >> 5, lane = tid & 31;
    const int el = lane >> 2, part = lane & 3;
    const int eidx = warp * 8 + el;          // block-local edge this lane owns
    const int cb = part * 4;                 // 4 m2 cols this lane owns

    const __half* pd = Pd + (size_t)sDc[eidx] * SP;
    const __half* ps = Ps + (size_t)sSc[eidx] * SP;
    const float n2 = sN2[eidx];
    float* sae = sA + eidx * SAE;            // this lane's edge row in sA

    // prefetch tile 0: 16 halves per array at [part*16, part*16+16)
    uint4 rpd[2], rps[2];
    {
        int off = part * 16;
        rpd[0] = *(const uint4*)(pd + off);
        rpd[1] = *(const uint4*)(pd + off + 8);
        rps[0] = *(const uint4*)(ps + off);
        rps[1] = *(const uint4*)(ps + off + 8);
    }

    ull a01 = 0, a23 = 0;

    for (int t = 0; t < 8; t++) {
        const int k0 = t * 64;
        // ---- convert + swish -> private sA slice ----
        #pragma unroll
        for (int j = 0; j < 2; j++) {
            uint4 va = (j == 0) ? rpd[0] : rpd[1];
            uint4 vb = (j == 0) ? rps[0] : rps[1];
            int off = part * 16 + j * 8;
            float4 aL = h4f4(make_uint2(va.x, va.y));
            float4 aH = h4f4(make_uint2(va.z, va.w));
            float4 bL = h4f4(make_uint2(vb.x, vb.y));
            float4 bH = h4f4(make_uint2(vb.z, vb.w));
            float4 wL = *(const float4*)(sWn + k0 + off);
            float4 wH = *(const float4*)(sWn + k0 + off + 4);
            float4 rL, rH;
            rL.x = swishf(aL.x + bL.x + n2 * wL.x);
            rL.y = swishf(aL.y + bL.y + n2 * wL.y);
            rL.z = swishf(aL.z + bL.z + n2 * wL.z);
            rL.w = swishf(aL.w + bL.w + n2 * wL.w);
            rH.x = swishf(aH.x + bH.x + n2 * wH.x);
            rH.y = swishf(aH.y + bH.y + n2 * wH.y);
            rH.z = swishf(aH.z + bH.z + n2 * wH.z);
            rH.w = swishf(aH.w + bH.w + n2 * wH.w);
            *(float4*)(sae + off) = rL;
            *(float4*)(sae + off + 4) = rH;
        }
        __syncwarp();
        // ---- prefetch tile t+1 (overlaps with GEMM below) ----
        if (t < 7) {
            int off = (t + 1) * 64 + part * 16;
            rpd[0] = *(const uint4*)(pd + off);
            rpd[1] = *(const uint4*)(pd + off + 8);
            rps[0] = *(const uint4*)(ps + off);
            rps[1] = *(const uint4*)(ps + off + 8);
        }
        // ---- mini-GEMM: this lane's edge row x sW2[:, cb..cb+3] ----
        #pragma unroll 4
        for (int kk = 0; kk < 64; kk += 4) {
            float4 av = *(const float4*)(sae + kk);
            #pragma unroll
            for (int q = 0; q < 4; q++) {
                float a = (q == 0) ? av.x : (q == 1) ? av.y : (q == 2) ? av.z : av.w;
                float4 wv = *(const float4*)(sW2 + (k0 + kk + q) * 16 + cb);
                ull w01 = *(ull*)&wv;
                ull w23 = *((ull*)&wv + 1);
                ull aa = pack2(a);
                fma2(a01, aa, w01);
                fma2(a23, aa, w23);
            }
        }
        __syncwarp();
    }

    // ---- tail k = 512..513 ----
    if (part == 0) {
        float4 a = h4f4(*(const uint2*)(pd + 512));
        float4 b = h4f4(*(const uint2*)(ps + 512));
        sae[0] = swishf(a.x + b.x + n2 * sWn[512]);
        sae[1] = swishf(a.y + b.y + n2 * sWn[513]);
    }
    __syncwarp();
    {
        float x0 = sae[0], x1 = sae[1];
        float4 w0 = *(const float4*)(sW2 + 512 * 16 + cb);
        float4 w1 = *(const float4*)(sW2 + 513 * 16 + cb);
        fma2(a01, pack2(x0), *(ull*)&w0);
        fma2(a23, pack2(x0), *((ull*)&w0 + 1));
        fma2(a01, pack2(x1), *(ull*)&w1);
        fma2(a23, pack2(x1), *((ull*)&w1 + 1));
    }

    // ---- epilogue: swish(m2 + b2) -> atomic scatter to agg[dst] ----
    int d = sDst[eidx];
    if (d >= 0) {
        float m0, m1, m2, m3;
        unpack2(a01, m0, m1);
        unpack2(a23, m2, m3);
        float* ap = agg + (size_t)d * FM_DIM + cb;
        atomicAdd(ap + 0, swishf(m0 + b2[cb + 0]));
        atomicAdd(ap + 1, swishf(m1 + b2[cb + 1]));
        atomicAdd(ap + 2, swishf(m2 + b2[cb + 2]));
        atomicAdd(ap + 3, swishf(m3 + b2[cb + 3]));
    }
}

// ---------------- fused node update ----------------
#define SU_STR 148
#define NODE_SMEM_BYTES ((64 * SU_STR + 64 * 132 + 8 * 132) * 4)

__global__ __launch_bounds__(256)
void node_update_kernel(const float* __restrict__ h,
                        const float* __restrict__ agg,
                        const float* __restrict__ W1, const float* __restrict__ b1,
                        const float* __restrict__ W2, const float* __restrict__ b2,
                        float* __restrict__ hout, int N) {
    extern __shared__ float sm[];
    float* sU  = sm;
    float* sU1 = sU + 64 * SU_STR;
    float* sB  = sU1 + 64 * 132;

    const int tid = threadIdx.x;
    const int n0 = blockIdx.x * 64;

    for (int idx = tid; idx < 64 * UIN; idx += 256) {
        int r = idx / UIN, c = idx % UIN;
        int node = n0 + r;
        float v = 0.0f;
        if (node < N)
            v = (c < FM_DIM) ? agg[(size_t)node * FM_DIM + c]
                             : h[(size_t)node * F_DIM + (c - FM_DIM)];
        sU[r * SU_STR + c] = v;
    }
    __syncthreads();

    const int ty = tid >> 4, tx = tid & 15;
    const int r0 = ty * 4, ct = tx * 8;

    float C2[4][8];
    #pragma unroll
    for (int i = 0; i < 4; i++)
        #pragma unroll
        for (int j = 0; j < 8; j++) C2[i][j] = 0.0f;

    for (int c0 = 0; c0 < UH; c0 += 128) {
        float C1[4][8];
        #pragma unroll
        for (int i = 0; i < 4; i++)
            #pragma unroll
            for (int j = 0; j < 8; j++) C1[i][j] = 0.0f;

        for (int k0 = 0; k0 < UIN; k0 += 8) {
            #pragma unroll
            for (int it = 0; it < 4; it++) {
                int t = tid + it * 256;
                int kk = t >> 7, c = t & 127;
                sB[kk * 132 + c] = W1[(size_t)(k0 + kk) * UH + c0 + c];
            }
            __syncthreads();
            #pragma unroll
            for (int kk = 0; kk < 8; kk++) {
                float4 b0 = *(const float4*)(sB + kk * 132 + ct);
                float4 b1v = *(const float4*)(sB + kk * 132 + ct + 4);
                #pragma unroll
                for (int i = 0; i < 4; i++) {
                    float a = sU[(r0 + i) * SU_STR + k0 + kk];
                    C1[i][0] += a * b0.x; C1[i][1] += a * b0.y;
                    C1[i][2] += a * b0.z; C1[i][3] += a * b0.w;
                    C1[i][4] += a * b1v.x; C1[i][5] += a * b1v.y;
                    C1[i][6] += a * b1v.z; C1[i][7] += a * b1v.w;
                }
            }
            __syncthreads();
        }
        #pragma unroll
        for (int i = 0; i < 4; i++)
            #pragma unroll
            for (int j = 0; j < 8; j++)
                sU1[(r0 + i) * 132 + ct + j] = swishf(C1[i][j] + b1[c0 + ct + j]);
        __syncthreads();

        for (int k0 = 0; k0 < 128; k0 += 8) {
            #pragma unroll
            for (int it = 0; it < 4; it++) {
                int t = tid + it * 256;
                int kk = t >> 7, c = t & 127;
                sB[kk * 132 + c] = W2[(size_t)(c0 + k0 + kk) * F_DIM + c];
            }
            __syncthreads();
            #pragma unroll
            for (int kk = 0; kk < 8; kk++) {
                float4 b0 = *(const float4*)(sB + kk * 132 + ct);
                float4 b1v = *(const float4*)(sB + kk * 132 + ct + 4);
                #pragma unroll
                for (int i = 0; i < 4; i++) {
                    float a = sU1[(r0 + i) * 132 + k0 + kk];
                    C2[i][0] += a * b0.x; C2[i][1] += a * b0.y;
                    C2[i][2] += a * b0.z; C2[i][3] += a * b0.w;
                    C2[i][4] += a * b1v.x; C2[i][5] += a * b1v.y;
                    C2[i][6] += a * b1v.z; C2[i][7] += a * b1v.w;
                }
            }
            __syncthreads();
        }
    }

    #pragma unroll
    for (int i = 0; i < 4; i++) {
        int node = n0 + r0 + i;
        if (node < N) {
            #pragma unroll
            for (int j = 0; j < 8; j++)
                hout[(size_t)node * F_DIM + ct + j] =
                    C2[i][j] + b2[ct + j] + sU[(r0 + i) * SU_STR + FM_DIM + ct + j];
        }
    }
}

// ---------------- projection + sorted-batch pooling ----------------
#define PROJ_SMEM_BYTES ((64 * 132 * 2 + 8 * 132) * 4 + 64 * 4)

__global__ __launch_bounds__(256)
void proj_pool_kernel(const float* __restrict__ h,
                      const int* __restrict__ batch,
                      const float* __restrict__ Wp1, const float* __restrict__ bp1,
                      const float* __restrict__ Wp2, const float* __restrict__ bp2,
                      float* __restrict__ pooled, int N) {
    extern __shared__ float sm[];
    float* sH = sm;
    float* sG = sH + 64 * 132;
    float* sB = sG + 64 * 132;
    int* sBatch = (int*)(sB + 8 * 132);

    const int tid = threadIdx.x;
    const int n0 = blockIdx.x * 64;

    for (int idx = tid; idx < 64 * HID; idx += 256) {
        int r = idx >> 7, c = idx & 127;
        int node = n0 + r;
        sH[r * 132 + c] = (node < N) ? h[(size_t)node * F_DIM + c] : 0.0f;
    }
    if (tid < 64) {
        int node = n0 + tid;
        sBatch[tid] = (node < N) ? batch[node] : -1;
    }
    __syncthreads();

    const int ty = tid >> 4, tx = tid & 15;
    const int r0 = ty * 4, ct = tx * 8;

    float C1[4][8];
    #pragma unroll
    for (int i = 0; i < 4; i++)
        #pragma unroll
        for (int j = 0; j < 8; j++) C1[i][j] = 0.0f;

    for (int k0 = 0; k0 < HID; k0 += 8) {
        #pragma unroll
        for (int it = 0; it < 4; it++) {
            int t = tid + it * 256;
            int kk = t >> 7, c = t & 127;
            sB[kk * 132 + c] = Wp1[(size_t)(k0 + kk) * HID + c];
        }
        __syncthreads();
        #pragma unroll
        for (int kk = 0; kk < 8; kk++) {
            float4 b0 = *(const float4*)(sB + kk * 132 + ct);
            float4 b1v = *(const float4*)(sB + kk * 132 + ct + 4);
            #pragma unroll
            for (int i = 0; i < 4; i++) {
                float a = sH[(r0 + i) * 132 + k0 + kk];
                C1[i][0] += a * b0.x; C1[i][1] += a * b0.y;
                C1[i][2] += a * b0.z; C1[i][3] += a * b0.w;
                C1[i][4] += a * b1v.x; C1[i][5] += a * b1v.y;
                C1[i][6] += a * b1v.z; C1[i][7] += a * b1v.w;
            }
        }
        __syncthreads();
    }
    #pragma unroll
    for (int i = 0; i < 4; i++)
        #pragma unroll
        for (int j = 0; j < 8; j++)
            sG[(r0 + i) * 132 + ct + j] = swishf(C1[i][j] + bp1[ct + j]);
    __syncthreads();

    float C2[4][8];
    #pragma unroll
    for (int i = 0; i < 4; i++)
        #pragma unroll
        for (int j = 0; j < 8; j++) C2[i][j] = 0.0f;

    for (int k0 = 0; k0 < HID; k0 += 8) {
        #pragma unroll
        for (int it = 0; it < 4; it++) {
            int t = tid + it * 256;
            int kk = t >> 7, c = t & 127;
            sB[kk * 132 + c] = Wp2[(size_t)(k0 + kk) * HID + c];
        }
        __syncthreads();
        #pragma unroll
        for (int kk = 0; kk < 8; kk++) {
            float4 b0 = *(const float4*)(sB + kk * 132 + ct);
            float4 b1v = *(const float4*)(sB + kk * 132 + ct + 4);
            #pragma unroll
            for (int i = 0; i < 4; i++) {
                float a = sG[(r0 + i) * 132 + k0 + kk];
                C2[i][0] += a * b0.x; C2[i][1] += a * b0.y;
                C2[i][2] += a * b0.z; C2[i][3] += a * b0.w;
                C2[i][4] += a * b1v.x; C2[i][5] += a * b1v.y;
                C2[i][6] += a * b1v.z; C2[i][7] += a * b1v.w;
            }
        }
        __syncthreads();
    }
    #pragma unroll
    for (int i = 0; i < 4; i++)
        #pragma unroll
        for (int j = 0; j < 8; j++)
            sH[(r0 + i) * 132 + ct + j] = C2[i][j] + bp2[ct + j];
    __syncthreads();

    if (tid < HID) {
        int col = tid;
        int g = sBatch[0];
        float acc = 0.0f;
        for (int r = 0; r < 64; r++) {
            int gg = sBatch[r];
            if (gg != g) {
                if (g >= 0) atomicAdd(&pooled[(size_t)g * HID + col], acc);
                acc = 0.0f;
                g = gg;
            }
            acc += sH[r * 132 + col];
        }
        if (g >= 0) atomicAdd(&pooled[(size_t)g * HID + col], acc);
    }
}

// ---------------- readout ----------------
#define RO_SMEM_BYTES ((64 * 132 * 2 + 8 * 132) * 4)

__global__ __launch_bounds__(256)
void readout_kernel(const float* __restrict__ pooled,
                    const float* __restrict__ Wr1, const float* __restrict__ br1,
                    const float* __restrict__ Wr2, const float* __restrict__ br2,
                    float* __restrict__ out, int G) {
    extern __shared__ float sm[];
    float* sP = sm;
    float* sR = sP + 64 * 132;
    float* sB = sR + 64 * 132;

    const int tid = threadIdx.x;
    const int g0 = blockIdx.x * 64;

    for (int idx = tid; idx < 64 * HID; idx += 256) {
        int r = idx >> 7, c = idx & 127;
        int g = g0 + r;
        sP[r * 132 + c] = (g < G) ? pooled[(size_t)g * HID + c] : 0.0f;
    }
    __syncthreads();

    const int ty = tid >> 4, tx = tid & 15;
    const int r0 = ty * 4, ct = tx * 8;

    float C1[4][8];
    #pragma unroll
    for (int i = 0; i < 4; i++)
        #pragma unroll
        for (int j = 0; j < 8; j++) C1[i][j] = 0.0f;

    for (int k0 = 0; k0 < HID; k0 += 8) {
        #pragma unroll
        for (int it = 0; it < 4; it++) {
            int t = tid + it * 256;
            int kk = t >> 7, c = t & 127;
            sB[kk * 132 + c] = Wr1[(size_t)(k0 + kk) * HID + c];
        }
        __syncthreads();
        #pragma unroll
        for (int kk = 0; kk < 8; kk++) {
            float4 b0 = *(const float4*)(sB + kk * 132 + ct);
            float4 b1v = *(const float4*)(sB + kk * 132 + ct + 4);
            #pragma unroll
            for (int i = 0; i < 4; i++) {
                float a = sP[(r0 + i) * 132 + k0 + kk];
                C1[i][0] += a * b0.x; C1[i][1] += a * b0.y;
                C1[i][2] += a * b0.z; C1[i][3] += a * b0.w;
                C1[i][4] += a * b1v.x; C1[i][5] += a * b1v.y;
                C1[i][6] += a * b1v.z; C1[i][7] += a * b1v.w;
            }
        }
        __syncthreads();
    }
    #pragma unroll
    for (int i = 0; i < 4; i++)
        #pragma unroll
        for (int j = 0; j < 8; j++)
            sR[(r0 + i) * 132 + ct + j] = swishf(C1[i][j] + br1[ct + j]);
    __syncthreads();

    for (int idx = tid; idx < 64 * T_OUT; idx += 256) {
        int e = idx / T_OUT, t = idx % T_OUT;
        int g = g0 + e;
        if (g < G) {
            float acc = br2[t];
            #pragma unroll 4
            for (int k = 0; k < HID; k++)
                acc += sR[e * 132 + k] * Wr2[(size_t)k * T_OUT + t];
            out[(size_t)g * T_OUT + t] = acc;
        }
    }
}

// ---------------- launch ----------------
extern "C" void kernel_launch(void* const* d_in, const int* in_sizes, int n_in,
                              void* d_out, int out_size) {
    const float* pos    = (const float*)d_in[0];
    const void*  zptr   = d_in[1];
    const int*   ei     = (const int*)d_in[2];
    const int*   batch  = (const int*)d_in[3];
    const float* emb    = (const float*)d_in[4];
    const float* W_msg1 = (const float*)d_in[5];
    const float* b_msg1 = (const float*)d_in[6];
    const float* W_msg2 = (const float*)d_in[7];
    const float* b_msg2 = (const float*)d_in[8];
    const float* W_up1  = (const float*)d_in[9];
    const float* b_up1  = (const float*)d_in[10];
    const float* W_up2  = (const float*)d_in[11];
    const float* b_up2  = (const float*)d_in[12];
    const float* Wp1    = (const float*)d_in[13];
    const float* bp1    = (const float*)d_in[14];
    const float* Wp2    = (const float*)d_in[15];
    const float* bp2    = (const float*)d_in[16];
    const float* Wr1    = (const float*)d_in[17];
    const float* br1    = (const float*)d_in[18];
    const float* Wr2    = (const float*)d_in[19];
    const float* br2    = (const float*)d_in[20];
    float* out = (float*)d_out;

    const int N = in_sizes[0] / 3;
    const int E = in_sizes[2] / 2;
    const int L = in_sizes[5] / (DIN * DH);
    const int G = out_size / T_OUT;

    float *h0, *h1, *aggp, *pooledp, *en2p;
    __half *pdp, *psp;
    int *curp, *esp, *edp;
    cudaGetSymbolAddress((void**)&h0, g_h0);
    cudaGetSymbolAddress((void**)&h1, g_h1);
    cudaGetSymbolAddress((void**)&aggp, g_agg);
    cudaGetSymbolAddress((void**)&pooledp, g_pooled);
    cudaGetSymbolAddress((void**)&en2p, g_en2);
    cudaGetSymbolAddress((void**)&pdp, g_Pd);
    cudaGetSymbolAddress((void**)&psp, g_Ps);
    cudaGetSymbolAddress((void**)&curp, g_cur);
    cudaGetSymbolAddress((void**)&esp, g_es);
    cudaGetSymbolAddress((void**)&edp, g_ed);

    cudaFuncSetAttribute(edge_kernel,
                         cudaFuncAttributeMaxDynamicSharedMemorySize, EDGE_SMEM_BYTES);
    cudaFuncSetAttribute(prep_gemm_kernel,
                         cudaFuncAttributeMaxDynamicSharedMemorySize, PREP_SMEM_BYTES);
    cudaFuncSetAttribute(node_update_kernel,
                         cudaFuncAttributeMaxDynamicSharedMemorySize, NODE_SMEM_BYTES);
    cudaFuncSetAttribute(proj_pool_kernel,
                         cudaFuncAttributeMaxDynamicSharedMemorySize, PROJ_SMEM_BYTES);
    cudaFuncSetAttribute(readout_kernel,
                         cudaFuncAttributeMaxDynamicSharedMemorySize, RO_SMEM_BYTES);

    // ---- one-time per launch: init h, counting-sort edges by dst ----
    init_h_kernel<<<(N * F_DIM + 255) / 256, 256>>>(zptr, emb, h0, N);
    izero_kernel<<<(N + 255) / 256, 256>>>(curp, N);
    hist_kernel<<<(E + 255) / 256, 256>>>(ei, curp, E);
    scan_kernel<<<1, 1024>>>(curp, curp, N);
    scatter_kernel<<<(E + 255) / 256, 256>>>(ei, pos, curp, esp, edp, en2p, E);

    const int nblk = (N + 63) / 64;
    const dim3 prep_grid(nblk, 5, 2);

    float* hc = h0;
    float* hn = h1;
    for (int l = 0; l < L; l++) {
        const float* W1l = W_msg1 + (size_t)l * DIN * DH;
        prep_gemm_kernel<<<prep_grid, 256, PREP_SMEM_BYTES>>>(
            hc, W1l, b_msg1 + (size_t)l * DH, pdp, psp, N);
        zero_kernel<<<(N * FM_DIM + 255) / 256, 256>>>(aggp, N * FM_DIM);
        edge_kernel<<<(E + EPB - 1) / EPB, 256, EDGE_SMEM_BYTES>>>(
            pdp, psp, W1l + (size_t)256 * DH,
            W_msg2 + (size_t)l * DH * FM_DIM, b_msg2 + (size_t)l * FM_DIM,
            esp, edp, en2p, aggp, E);
        node_update_kernel<<<nblk, 256, NODE_SMEM_BYTES>>>(
            hc, aggp,
            W_up1 + (size_t)l * UIN * UH, b_up1 + (size_t)l * UH,
            W_up2 + (size_t)l * UH * F_DIM, b_up2 + (size_t)l * F_DIM,
            hn, N);
        float* t = hc; hc = hn; hn = t;
    }

    zero_kernel<<<(G * HID + 255) / 256, 256>>>(pooledp, G * HID);
    proj_pool_kernel<<<nblk, 256, PROJ_SMEM_BYTES>>>(
        hc, batch, Wp1, bp1, Wp2, bp2, pooledp, N);
    readout_kernel<<<(G + 63) / 64, 256, RO_SMEM_BYTES>>>(
        pooledp, Wr1, br1, Wr2, br2, out, G);
}

// round 9
// speedup vs baseline: 1.1482x; 1.1482x over previous
#include <cuda_runtime.h>
#include <cuda_fp16.h>
#include <cstdint>

#define F_DIM   128
#define FM_DIM  16
#define DIN     257
#define DH      514
#define UIN     144
#define UH      256
#define HID     128
#define T_OUT   12
#define SP      520     // padded row stride for Pd/Ps in HALVES (1040B, 16B-aligned)

#define MAXN 50048
#define MAXE 800000
#define MAXG 1024

// ---------------- scratch (no allocations allowed) ----------------
__device__ __align__(256) float  g_h0[MAXN * F_DIM];
__device__ __align__(256) float  g_h1[MAXN * F_DIM];
__device__ __align__(256) float  g_en2[MAXE];      // norm2, dst-sorted order
__device__ __align__(256) float  g_agg[MAXN * FM_DIM];
__device__ __align__(256) float  g_pooled[MAXG * HID];
__device__ __align__(256) __half g_Pd[MAXN * SP];  // h @ W1[0:128] + b1   (fp16)
__device__ __align__(256) __half g_Ps[MAXN * SP];  // h @ W1[128:256]      (fp16)
__device__ __align__(256) int    g_cur[MAXN];      // scan cursor
__device__ __align__(256) int    g_es[MAXE];       // sorted src
__device__ __align__(256) int    g_ed[MAXE];       // sorted dst

// ---------------- helpers ----------------
__device__ __forceinline__ float swishf(float x) {
    return __fdividef(x, 1.0f + __expf(-x));
}

// 1-MUFU swish: e = ex2(-|x|*log2e) in (0,1], d = 1+e in (1,2],
// rcp(d) via bit-trick seed + 2 Newton steps (FMA only, rel err ~7e-6).
__device__ __forceinline__ float fast_swish(float x) {
    float e;
    asm("ex2.approx.ftz.f32 %0, %1;" : "=f"(e) : "f"(-fabsf(x) * 1.44269504f));
    float d = 1.0f + e;
    float r = __uint_as_float(0x7EF311C3u - __float_as_uint(d));
    r = r * (2.0f - d * r);
    r = r * (2.0f - d * r);
    float s = (x >= 0.0f) ? r : e * r;   // sigmoid(x)
    return x * s;
}

typedef unsigned long long ull;

__device__ __forceinline__ void fma2(ull& d, ull a, ull b) {
    asm("fma.rn.f32x2 %0, %1, %2, %0;" : "+l"(d) : "l"(a), "l"(b));
}
__device__ __forceinline__ ull pack2(float x) {
    ull r;
    asm("mov.b64 %0, {%1, %1};" : "=l"(r) : "f"(x));
    return r;
}
__device__ __forceinline__ void unpack2(ull v, float& lo, float& hi) {
    asm("mov.b64 {%0, %1}, %2;" : "=f"(lo), "=f"(hi) : "l"(v));
}
// 4 packed halves -> float4
__device__ __forceinline__ float4 h4f4(uint2 v) {
    __half2 h0 = *(__half2*)&v.x;
    __half2 h1 = *(__half2*)&v.y;
    float2 f0 = __half22float2(h0);
    float2 f1 = __half22float2(h1);
    return make_float4(f0.x, f0.y, f1.x, f1.y);
}

// ---------------- small kernels ----------------
__global__ void zero_kernel(float* p, int n) {
    int i = blockIdx.x * blockDim.x + threadIdx.x;
    if (i < n) p[i] = 0.0f;
}
__global__ void izero_kernel(int* p, int n) {
    int i = blockIdx.x * blockDim.x + threadIdx.x;
    if (i < n) p[i] = 0;
}

__global__ void init_h_kernel(const void* zptr, const float* __restrict__ emb,
                              float* __restrict__ h, int N) {
    int i = blockIdx.x * blockDim.x + threadIdx.x;
    if (i >= N * F_DIM) return;
    int node = i / F_DIM, f = i % F_DIM;
    const int* z32 = (const int*)zptr;
    bool is64 = (z32[1] == 0) && (z32[3] == 0) && (z32[5] == 0);
    long long zv = is64 ? ((const long long*)zptr)[node] : (long long)z32[node];
    int e = (zv == 1) ? 0 : (int)(zv - 5);
    h[i] = emb[e * F_DIM + f];
}

// ---------------- counting sort of edges by dst ----------------
__global__ void hist_kernel(const int* __restrict__ ei, int* __restrict__ cnt, int E) {
    int e = blockIdx.x * blockDim.x + threadIdx.x;
    if (e < E) atomicAdd(&cnt[ei[E + e]], 1);
}

__global__ void scan_kernel(int* __restrict__ cnt, int* __restrict__ cur, int N) {
    __shared__ int sdata[1024];
    __shared__ int carry_s;
    if (threadIdx.x == 0) carry_s = 0;
    __syncthreads();
    for (int base = 0; base < N; base += 1024) {
        int i = base + threadIdx.x;
        int v = (i < N) ? cnt[i] : 0;
        sdata[threadIdx.x] = v;
        __syncthreads();
        for (int ofs = 1; ofs < 1024; ofs <<= 1) {
            int t = (threadIdx.x >= ofs) ? sdata[threadIdx.x - ofs] : 0;
            __syncthreads();
            sdata[threadIdx.x] += t;
            __syncthreads();
        }
        int excl = sdata[threadIdx.x] - v + carry_s;
        if (i < N) cur[i] = excl;
        __syncthreads();
        if (threadIdx.x == 0) carry_s += sdata[1023];
        __syncthreads();
    }
}

__global__ void scatter_kernel(const int* __restrict__ ei, const float* __restrict__ pos,
                               int* __restrict__ cur,
                               int* __restrict__ es, int* __restrict__ ed,
                               float* __restrict__ en2, int E) {
    int e = blockIdx.x * blockDim.x + threadIdx.x;
    if (e >= E) return;
    int s = ei[e], d = ei[E + e];
    float dx = pos[s * 3 + 0] - pos[d * 3 + 0];
    float dy = pos[s * 3 + 1] - pos[d * 3 + 1];
    float dz = pos[s * 3 + 2] - pos[d * 3 + 2];
    int p = atomicAdd(&cur[d], 1);
    es[p] = s; ed[p] = d;
    en2[p] = dx * dx + dy * dy + dz * dz;
}

// ---------------- per-node pre-GEMM: P = h @ W (+bias), fp16 out ----------
#define PREP_SMEM_BYTES ((64 * 132 + 8 * 132) * 4)

__global__ __launch_bounds__(256)
void prep_gemm_kernel(const float* __restrict__ h, const float* __restrict__ W1,
                      const float* __restrict__ bias,
                      __half* __restrict__ Pd, __half* __restrict__ Ps, int N) {
    extern __shared__ float sm[];
    float* sH = sm;             // 64 x 132
    float* sB = sH + 64 * 132;  // 8 x 132

    const int tid = threadIdx.x;
    const int n0 = blockIdx.x * 64;
    const int c0 = blockIdx.y * 128;
    const int which = blockIdx.z;
    const float* W = W1 + (size_t)which * 128 * DH;
    __half* P = which ? Ps : Pd;

    for (int idx = tid; idx < 64 * 128; idx += 256) {
        int r = idx >> 7, c = idx & 127;
        int node = n0 + r;
        sH[r * 132 + c] = (node < N) ? h[(size_t)node * F_DIM + c] : 0.0f;
    }
    __syncthreads();

    const int ty = tid >> 4, tx = tid & 15;
    const int r0 = ty * 4, ct = tx * 8;

    ull C01[4], C23[4], C45[4], C67[4];
    #pragma unroll
    for (int i = 0; i < 4; i++) { C01[i] = 0; C23[i] = 0; C45[i] = 0; C67[i] = 0; }

    for (int k0 = 0; k0 < 128; k0 += 8) {
        #pragma unroll
        for (int it = 0; it < 4; it++) {
            int t = tid + it * 256;
            int kk = t >> 7, c = t & 127;
            int col = c0 + c;
            sB[kk * 132 + c] = (col < DH) ? W[(size_t)(k0 + kk) * DH + col] : 0.0f;
        }
        __syncthreads();
        #pragma unroll
        for (int kk = 0; kk < 8; kk++) {
            const float* bp = sB + kk * 132 + ct;
            ull b01 = *(const ull*)(bp);
            ull b23 = *(const ull*)(bp + 2);
            ull b45 = *(const ull*)(bp + 4);
            ull b67 = *(const ull*)(bp + 6);
            #pragma unroll
            for (int i = 0; i < 4; i++) {
                ull aa = pack2(sH[(r0 + i) * 132 + k0 + kk]);
                fma2(C01[i], aa, b01); fma2(C23[i], aa, b23);
                fma2(C45[i], aa, b45); fma2(C67[i], aa, b67);
            }
        }
        __syncthreads();
    }

    #pragma unroll
    for (int i = 0; i < 4; i++) {
        int node = n0 + r0 + i;
        if (node >= N) continue;
        float v[8];
        unpack2(C01[i], v[0], v[1]); unpack2(C23[i], v[2], v[3]);
        unpack2(C45[i], v[4], v[5]); unpack2(C67[i], v[6], v[7]);
        int col0 = c0 + ct;
        __half* prow = P + (size_t)node * SP + col0;
        #pragma unroll
        for (int j = 0; j < 8; j++)
            v[j] += (which == 0 && col0 + j < DH) ? bias[col0 + j] : 0.0f;
        if (col0 + 8 <= DH) {
            __half2 h01 = __floats2half2_rn(v[0], v[1]);
            __half2 h23 = __floats2half2_rn(v[2], v[3]);
            __half2 h45 = __floats2half2_rn(v[4], v[5]);
            __half2 h67 = __floats2half2_rn(v[6], v[7]);
            uint4 st;
            st.x = *(unsigned*)&h01; st.y = *(unsigned*)&h23;
            st.z = *(unsigned*)&h45; st.w = *(unsigned*)&h67;
            *(uint4*)prow = st;
        } else {
            #pragma unroll
            for (int j = 0; j < 8; j++)
                if (col0 + j < SP)
                    prow[j] = __float2half_rn((col0 + j < DH) ? v[j] : 0.0f);
        }
    }
}

// ---------------- edge phase (dst-sorted, fp16 gather, reg prefetch) ------
#define EPB 128
#define SAE 68
#define EDGE_SMEM_FLOATS (516 * 16 + 516 + EPB * SAE)
#define EDGE_SMEM_BYTES  (EDGE_SMEM_FLOATS * 4 + EPB * 4 * 4)

__global__ __launch_bounds__(256, 2)
void edge_kernel(const __half* __restrict__ Pd, const __half* __restrict__ Ps,
                 const float* __restrict__ Wn,   // W1 row 256 (norm2 row)
                 const float* __restrict__ W2, const float* __restrict__ b2,
                 const int* __restrict__ es, const int* __restrict__ ed,
                 const float* __restrict__ en2,
                 float* __restrict__ agg, int E) {
    extern __shared__ float sm[];
    float* sW2 = sm;                 // 516 x 16 (rows >=514 zero)
    float* sWn = sW2 + 516 * 16;     // 516 (pad zero)
    float* sA  = sWn + 516;          // 128 x 68 (swished m1 tile)
    int*   sDst = (int*)(sA + EPB * SAE);
    int*   sDc  = sDst + EPB;
    int*   sSc  = sDc + EPB;
    float* sN2  = (float*)(sSc + EPB);

    const int tid = threadIdx.x;
    const int e0 = blockIdx.x * EPB;

    for (int i = tid; i < 516 * 16; i += 256) {
        int k = i >> 4;
        sW2[i] = (k < DH) ? W2[i] : 0.0f;
    }
    for (int i = tid; i < 516; i += 256)
        sWn[i] = (i < DH) ? Wn[i] : 0.0f;
    if (tid < EPB) {
        int e = e0 + tid;
        if (e < E) {
            sDst[tid] = ed[e]; sDc[tid] = ed[e]; sSc[tid] = es[e];
            sN2[tid] = en2[e];
        } else {
            sDst[tid] = -1; sDc[tid] = 0; sSc[tid] = 0; sN2[tid] = 0.0f;
        }
    }
    __syncthreads();

    const int part = tid & 3, eg = tid >> 2;   // eg in [0,64)

    const __half* pdp[2];
    const __half* psp[2];
    float n2v[2];
    #pragma unroll
    for (int p = 0; p < 2; p++) {
        int e = p * 64 + eg;
        pdp[p] = Pd + (size_t)sDc[e] * SP;
        psp[p] = Ps + (size_t)sSc[e] * SP;
        n2v[p] = sN2[e];
    }

    // prefetch tile 0
    uint2 rpd[2][4], rps[2][4];
    #pragma unroll
    for (int p = 0; p < 2; p++)
        #pragma unroll
        for (int i = 0; i < 4; i++) {
            int off = i * 16 + part * 4;
            rpd[p][i] = *(const uint2*)(pdp[p] + off);
            rps[p][i] = *(const uint2*)(psp[p] + off);
        }

    const int r0y = (tid >> 2) * 2;     // 2 edge rows per thread in GEMM
    const int cb  = (tid & 3) * 4;      // 4 m2 cols per thread
    ull acc01[2], acc23[2];
    acc01[0] = acc01[1] = acc23[0] = acc23[1] = 0;

    for (int t = 0; t < 8; t++) {
        const int k0 = t * 64;
        // ---- convert prefetched regs + swish -> sA ----
        #pragma unroll
        for (int p = 0; p < 2; p++) {
            int e = p * 64 + eg;
            float n2 = n2v[p];
            float* sa = sA + e * SAE;
            #pragma unroll
            for (int i = 0; i < 4; i++) {
                int off = i * 16 + part * 4;
                float4 a = h4f4(rpd[p][i]);
                float4 b = h4f4(rps[p][i]);
                float4 w = *(const float4*)(sWn + k0 + off);
                float4 r;
                r.x = fast_swish(a.x + b.x + n2 * w.x);
                r.y = fast_swish(a.y + b.y + n2 * w.y);
                r.z = fast_swish(a.z + b.z + n2 * w.z);
                r.w = fast_swish(a.w + b.w + n2 * w.w);
                *(float4*)(sa + off) = r;
            }
        }
        __syncthreads();
        // ---- issue gathers for tile t+1 (overlap with GEMM below) ----
        if (t < 7) {
            #pragma unroll
            for (int p = 0; p < 2; p++)
                #pragma unroll
                for (int i = 0; i < 4; i++) {
                    int off = (t + 1) * 64 + i * 16 + part * 4;
                    rpd[p][i] = *(const uint2*)(pdp[p] + off);
                    rps[p][i] = *(const uint2*)(psp[p] + off);
                }
        }
        // ---- mini-GEMM: acc += sA[rows, k] * sW2[k, cols] ----
        for (int kk = 0; kk < 64; kk += 4) {
            float4 av0 = *(const float4*)(sA + r0y * SAE + kk);
            float4 av1 = *(const float4*)(sA + (r0y + 1) * SAE + kk);
            #pragma unroll
            for (int q = 0; q < 4; q++) {
                const float* wp = sW2 + (k0 + kk + q) * 16 + cb;
                ull w01 = *(const ull*)(wp);
                ull w23 = *(const ull*)(wp + 2);
                float a0 = (q == 0) ? av0.x : (q == 1) ? av0.y : (q == 2) ? av0.z : av0.w;
                float a1 = (q == 0) ? av1.x : (q == 1) ? av1.y : (q == 2) ? av1.z : av1.w;
                fma2(acc01[0], pack2(a0), w01); fma2(acc23[0], pack2(a0), w23);
                fma2(acc01[1], pack2(a1), w01); fma2(acc23[1], pack2(a1), w23);
            }
        }
        __syncthreads();
    }

    // ---- tail k = 512..513 ----
    if (tid < EPB) {
        const __half* pd = Pd + (size_t)sDc[tid] * SP + 512;
        const __half* ps = Ps + (size_t)sSc[tid] * SP + 512;
        float4 a = h4f4(*(const uint2*)pd);
        float4 b = h4f4(*(const uint2*)ps);
        float n2 = sN2[tid];
        float* sa = sA + tid * SAE;
        sa[0] = fast_swish(a.x + b.x + n2 * sWn[512]);
        sa[1] = fast_swish(a.y + b.y + n2 * sWn[513]);
    }
    __syncthreads();
    {
        float a00 = sA[r0y * SAE + 0], a01 = sA[r0y * SAE + 1];
        float a10 = sA[(r0y + 1) * SAE + 0], a11 = sA[(r0y + 1) * SAE + 1];
        const float* wp0 = sW2 + 512 * 16 + cb;
        const float* wp1 = sW2 + 513 * 16 + cb;
        ull w01a = *(const ull*)(wp0), w23a = *(const ull*)(wp0 + 2);
        ull w01b = *(const ull*)(wp1), w23b = *(const ull*)(wp1 + 2);
        fma2(acc01[0], pack2(a00), w01a); fma2(acc23[0], pack2(a00), w23a);
        fma2(acc01[0], pack2(a01), w01b); fma2(acc23[0], pack2(a01), w23b);
        fma2(acc01[1], pack2(a10), w01a); fma2(acc23[1], pack2(a10), w23a);
        fma2(acc01[1], pack2(a11), w01b); fma2(acc23[1], pack2(a11), w23b);
    }

    // ---- epilogue: swish(m2 + b2), merge same-dst pair, atomic scatter ----
    float bb0 = b2[cb], bb1 = b2[cb + 1], bb2 = b2[cb + 2], bb3 = b2[cb + 3];
    int d0 = sDst[r0y], d1 = sDst[r0y + 1];
    float m00, m01, m02, m03, m10, m11, m12, m13;
    unpack2(acc01[0], m00, m01); unpack2(acc23[0], m02, m03);
    unpack2(acc01[1], m10, m11); unpack2(acc23[1], m12, m13);
    float v00 = fast_swish(m00 + bb0), v01 = fast_swish(m01 + bb1);
    float v02 = fast_swish(m02 + bb2), v03 = fast_swish(m03 + bb3);
    float v10 = fast_swish(m10 + bb0), v11 = fast_swish(m11 + bb1);
    float v12 = fast_swish(m12 + bb2), v13 = fast_swish(m13 + bb3);
    if (d0 == d1) {
        if (d0 >= 0) {
            float* ap = agg + (size_t)d0 * FM_DIM + cb;
            atomicAdd(ap + 0, v00 + v10); atomicAdd(ap + 1, v01 + v11);
            atomicAdd(ap + 2, v02 + v12); atomicAdd(ap + 3, v03 + v13);
        }
    } else {
        if (d0 >= 0) {
            float* ap = agg + (size_t)d0 * FM_DIM + cb;
            atomicAdd(ap + 0, v00); atomicAdd(ap + 1, v01);
            atomicAdd(ap + 2, v02); atomicAdd(ap + 3, v03);
        }
        if (d1 >= 0) {
            float* ap = agg + (size_t)d1 * FM_DIM + cb;
            atomicAdd(ap + 0, v10); atomicAdd(ap + 1, v11);
            atomicAdd(ap + 2, v12); atomicAdd(ap + 3, v13);
        }
    }
}

// ---------------- fused node update ----------------
#define SU_STR 148
#define NODE_SMEM_BYTES ((64 * SU_STR + 64 * 132 + 8 * 132) * 4)

__global__ __launch_bounds__(256)
void node_update_kernel(const float* __restrict__ h,
                        const float* __restrict__ agg,
                        const float* __restrict__ W1, const float* __restrict__ b1,
                        const float* __restrict__ W2, const float* __restrict__ b2,
                        float* __restrict__ hout, int N) {
    extern __shared__ float sm[];
    float* sU  = sm;
    float* sU1 = sU + 64 * SU_STR;
    float* sB  = sU1 + 64 * 132;

    const int tid = threadIdx.x;
    const int n0 = blockIdx.x * 64;

    for (int idx = tid; idx < 64 * UIN; idx += 256) {
        int r = idx / UIN, c = idx % UIN;
        int node = n0 + r;
        float v = 0.0f;
        if (node < N)
            v = (c < FM_DIM) ? agg[(size_t)node * FM_DIM + c]
                             : h[(size_t)node * F_DIM + (c - FM_DIM)];
        sU[r * SU_STR + c] = v;
    }
    __syncthreads();

    const int ty = tid >> 4, tx = tid & 15;
    const int r0 = ty * 4, ct = tx * 8;

    float C2[4][8];
    #pragma unroll
    for (int i = 0; i < 4; i++)
        #pragma unroll
        for (int j = 0; j < 8; j++) C2[i][j] = 0.0f;

    for (int c0 = 0; c0 < UH; c0 += 128) {
        float C1[4][8];
        #pragma unroll
        for (int i = 0; i < 4; i++)
            #pragma unroll
            for (int j = 0; j < 8; j++) C1[i][j] = 0.0f;

        for (int k0 = 0; k0 < UIN; k0 += 8) {
            #pragma unroll
            for (int it = 0; it < 4; it++) {
                int t = tid + it * 256;
                int kk = t >> 7, c = t & 127;
                sB[kk * 132 + c] = W1[(size_t)(k0 + kk) * UH + c0 + c];
            }
            __syncthreads();
            #pragma unroll
            for (int kk = 0; kk < 8; kk++) {
                float4 b0 = *(const float4*)(sB + kk * 132 + ct);
                float4 b1v = *(const float4*)(sB + kk * 132 + ct + 4);
                #pragma unroll
                for (int i = 0; i < 4; i++) {
                    float a = sU[(r0 + i) * SU_STR + k0 + kk];
                    C1[i][0] += a * b0.x; C1[i][1] += a * b0.y;
                    C1[i][2] += a * b0.z; C1[i][3] += a * b0.w;
                    C1[i][4] += a * b1v.x; C1[i][5] += a * b1v.y;
                    C1[i][6] += a * b1v.z; C1[i][7] += a * b1v.w;
                }
            }
            __syncthreads();
        }
        #pragma unroll
        for (int i = 0; i < 4; i++)
            #pragma unroll
            for (int j = 0; j < 8; j++)
                sU1[(r0 + i) * 132 + ct + j] = swishf(C1[i][j] + b1[c0 + ct + j]);
        __syncthreads();

        for (int k0 = 0; k0 < 128; k0 += 8) {
            #pragma unroll
            for (int it = 0; it < 4; it++) {
                int t = tid + it * 256;
                int kk = t >> 7, c = t & 127;
                sB[kk * 132 + c] = W2[(size_t)(c0 + k0 + kk) * F_DIM + c];
            }
            __syncthreads();
            #pragma unroll
            for (int kk = 0; kk < 8; kk++) {
                float4 b0 = *(const float4*)(sB + kk * 132 + ct);
                float4 b1v = *(const float4*)(sB + kk * 132 + ct + 4);
                #pragma unroll
                for (int i = 0; i < 4; i++) {
                    float a = sU1[(r0 + i) * 132 + k0 + kk];
                    C2[i][0] += a * b0.x; C2[i][1] += a * b0.y;
                    C2[i][2] += a * b0.z; C2[i][3] += a * b0.w;
                    C2[i][4] += a * b1v.x; C2[i][5] += a * b1v.y;
                    C2[i][6] += a * b1v.z; C2[i][7] += a * b1v.w;
                }
            }
            __syncthreads();
        }
    }

    #pragma unroll
    for (int i = 0; i < 4; i++) {
        int node = n0 + r0 + i;
        if (node < N) {
            #pragma unroll
            for (int j = 0; j < 8; j++)
                hout[(size_t)node * F_DIM + ct + j] =
                    C2[i][j] + b2[ct + j] + sU[(r0 + i) * SU_STR + FM_DIM + ct + j];
        }
    }
}

// ---------------- projection + sorted-batch pooling ----------------
#define PROJ_SMEM_BYTES ((64 * 132 * 2 + 8 * 132) * 4 + 64 * 4)

__global__ __launch_bounds__(256)
void proj_pool_kernel(const float* __restrict__ h,
                      const int* __restrict__ batch,
                      const float* __restrict__ Wp1, const float* __restrict__ bp1,
                      const float* __restrict__ Wp2, const float* __restrict__ bp2,
                      float* __restrict__ pooled, int N) {
    extern __shared__ float sm[];
    float* sH = sm;
    float* sG = sH + 64 * 132;
    float* sB = sG + 64 * 132;
    int* sBatch = (int*)(sB + 8 * 132);

    const int tid = threadIdx.x;
    const int n0 = blockIdx.x * 64;

    for (int idx = tid; idx < 64 * HID; idx += 256) {
        int r = idx >> 7, c = idx & 127;
        int node = n0 + r;
        sH[r * 132 + c] = (node < N) ? h[(size_t)node * F_DIM + c] : 0.0f;
    }
    if (tid < 64) {
        int node = n0 + tid;
        sBatch[tid] = (node < N) ? batch[node] : -1;
    }
    __syncthreads();

    const int ty = tid >> 4, tx = tid & 15;
    const int r0 = ty * 4, ct = tx * 8;

    float C1[4][8];
    #pragma unroll
    for (int i = 0; i < 4; i++)
        #pragma unroll
        for (int j = 0; j < 8; j++) C1[i][j] = 0.0f;

    for (int k0 = 0; k0 < HID; k0 += 8) {
        #pragma unroll
        for (int it = 0; it < 4; it++) {
            int t = tid + it * 256;
            int kk = t >> 7, c = t & 127;
            sB[kk * 132 + c] = Wp1[(size_t)(k0 + kk) * HID + c];
        }
        __syncthreads();
        #pragma unroll
        for (int kk = 0; kk < 8; kk++) {
            float4 b0 = *(const float4*)(sB + kk * 132 + ct);
            float4 b1v = *(const float4*)(sB + kk * 132 + ct + 4);
            #pragma unroll
            for (int i = 0; i < 4; i++) {
                float a = sH[(r0 + i) * 132 + k0 + kk];
                C1[i][0] += a * b0.x; C1[i][1] += a * b0.y;
                C1[i][2] += a * b0.z; C1[i][3] += a * b0.w;
                C1[i][4] += a * b1v.x; C1[i][5] += a * b1v.y;
                C1[i][6] += a * b1v.z; C1[i][7] += a * b1v.w;
            }
        }
        __syncthreads();
    }
    #pragma unroll
    for (int i = 0; i < 4; i++)
        #pragma unroll
        for (int j = 0; j < 8; j++)
            sG[(r0 + i) * 132 + ct + j] = swishf(C1[i][j] + bp1[ct + j]);
    __syncthreads();

    float C2[4][8];
    #pragma unroll
    for (int i = 0; i < 4; i++)
        #pragma unroll
        for (int j = 0; j < 8; j++) C2[i][j] = 0.0f;

    for (int k0 = 0; k0 < HID; k0 += 8) {
        #pragma unroll
        for (int it = 0; it < 4; it++) {
            int t = tid + it * 256;
            int kk = t >> 7, c = t & 127;
            sB[kk * 132 + c] = Wp2[(size_t)(k0 + kk) * HID + c];
        }
        __syncthreads();
        #pragma unroll
        for (int kk = 0; kk < 8; kk++) {
            float4 b0 = *(const float4*)(sB + kk * 132 + ct);
            float4 b1v = *(const float4*)(sB + kk * 132 + ct + 4);
            #pragma unroll
            for (int i = 0; i < 4; i++) {
                float a = sG[(r0 + i) * 132 + k0 + kk];
                C2[i][0] += a * b0.x; C2[i][1] += a * b0.y;
                C2[i][2] += a * b0.z; C2[i][3] += a * b0.w;
                C2[i][4] += a * b1v.x; C2[i][5] += a * b1v.y;
                C2[i][6] += a * b1v.z; C2[i][7] += a * b1v.w;
            }
        }
        __syncthreads();
    }
    #pragma unroll
    for (int i = 0; i < 4; i++)
        #pragma unroll
        for (int j = 0; j < 8; j++)
            sH[(r0 + i) * 132 + ct + j] = C2[i][j] + bp2[ct + j];
    __syncthreads();

    if (tid < HID) {
        int col = tid;
        int g = sBatch[0];
        float acc = 0.0f;
        for (int r = 0; r < 64; r++) {
            int gg = sBatch[r];
            if (gg != g) {
                if (g >= 0) atomicAdd(&pooled[(size_t)g * HID + col], acc);
                acc = 0.0f;
                g = gg;
            }
            acc += sH[r * 132 + col];
        }
        if (g >= 0) atomicAdd(&pooled[(size_t)g * HID + col], acc);
    }
}

// ---------------- readout ----------------
#define RO_SMEM_BYTES ((64 * 132 * 2 + 8 * 132) * 4)

__global__ __launch_bounds__(256)
void readout_kernel(const float* __restrict__ pooled,
                    const float* __restrict__ Wr1, const float* __restrict__ br1,
                    const float* __restrict__ Wr2, const float* __restrict__ br2,
                    float* __restrict__ out, int G) {
    extern __shared__ float sm[];
    float* sP = sm;
    float* sR = sP + 64 * 132;
    float* sB = sR + 64 * 132;

    const int tid = threadIdx.x;
    const int g0 = blockIdx.x * 64;

    for (int idx = tid; idx < 64 * HID; idx += 256) {
        int r = idx >> 7, c = idx & 127;
        int g = g0 + r;
        sP[r * 132 + c] = (g < G) ? pooled[(size_t)g * HID + c] : 0.0f;
    }
    __syncthreads();

    const int ty = tid >> 4, tx = tid & 15;
    const int r0 = ty * 4, ct = tx * 8;

    float C1[4][8];
    #pragma unroll
    for (int i = 0; i < 4; i++)
        #pragma unroll
        for (int j = 0; j < 8; j++) C1[i][j] = 0.0f;

    for (int k0 = 0; k0 < HID; k0 += 8) {
        #pragma unroll
        for (int it = 0; it < 4; it++) {
            int t = tid + it * 256;
            int kk = t >> 7, c = t & 127;
            sB[kk * 132 + c] = Wr1[(size_t)(k0 + kk) * HID + c];
        }
        __syncthreads();
        #pragma unroll
        for (int kk = 0; kk < 8; kk++) {
            float4 b0 = *(const float4*)(sB + kk * 132 + ct);
            float4 b1v = *(const float4*)(sB + kk * 132 + ct + 4);
            #pragma unroll
            for (int i = 0; i < 4; i++) {
                float a = sP[(r0 + i) * 132 + k0 + kk];
                C1[i][0] += a * b0.x; C1[i][1] += a * b0.y;
                C1[i][2] += a * b0.z; C1[i][3] += a * b0.w;
                C1[i][4] += a * b1v.x; C1[i][5] += a * b1v.y;
                C1[i][6] += a * b1v.z; C1[i][7] += a * b1v.w;
            }
        }
        __syncthreads();
    }
    #pragma unroll
    for (int i = 0; i < 4; i++)
        #pragma unroll
        for (int j = 0; j < 8; j++)
            sR[(r0 + i) * 132 + ct + j] = swishf(C1[i][j] + br1[ct + j]);
    __syncthreads();

    for (int idx = tid; idx < 64 * T_OUT; idx += 256) {
        int e = idx / T_OUT, t = idx % T_OUT;
        int g = g0 + e;
        if (g < G) {
            float acc = br2[t];
            #pragma unroll 4
            for (int k = 0; k < HID; k++)
                acc += sR[e * 132 + k] * Wr2[(size_t)k * T_OUT + t];
            out[(size_t)g * T_OUT + t] = acc;
        }
    }
}

// ---------------- launch ----------------
extern "C" void kernel_launch(void* const* d_in, const int* in_sizes, int n_in,
                              void* d_out, int out_size) {
    const float* pos    = (const float*)d_in[0];
    const void*  zptr   = d_in[1];
    const int*   ei     = (const int*)d_in[2];
    const int*   batch  = (const int*)d_in[3];
    const float* emb    = (const float*)d_in[4];
    const float* W_msg1 = (const float*)d_in[5];
    const float* b_msg1 = (const float*)d_in[6];
    const float* W_msg2 = (const float*)d_in[7];
    const float* b_msg2 = (const float*)d_in[8];
    const float* W_up1  = (const float*)d_in[9];
    const float* b_up1  = (const float*)d_in[10];
    const float* W_up2  = (const float*)d_in[11];
    const float* b_up2  = (const float*)d_in[12];
    const float* Wp1    = (const float*)d_in[13];
    const float* bp1    = (const float*)d_in[14];
    const float* Wp2    = (const float*)d_in[15];
    const float* bp2    = (const float*)d_in[16];
    const float* Wr1    = (const float*)d_in[17];
    const float* br1    = (const float*)d_in[18];
    const float* Wr2    = (const float*)d_in[19];
    const float* br2    = (const float*)d_in[20];
    float* out = (float*)d_out;

    const int N = in_sizes[0] / 3;
    const int E = in_sizes[2] / 2;
    const int L = in_sizes[5] / (DIN * DH);
    const int G = out_size / T_OUT;

    float *h0, *h1, *aggp, *pooledp, *en2p;
    __half *pdp, *psp;
    int *curp, *esp, *edp;
    cudaGetSymbolAddress((void**)&h0, g_h0);
    cudaGetSymbolAddress((void**)&h1, g_h1);
    cudaGetSymbolAddress((void**)&aggp, g_agg);
    cudaGetSymbolAddress((void**)&pooledp, g_pooled);
    cudaGetSymbolAddress((void**)&en2p, g_en2);
    cudaGetSymbolAddress((void**)&pdp, g_Pd);
    cudaGetSymbolAddress((void**)&psp, g_Ps);
    cudaGetSymbolAddress((void**)&curp, g_cur);
    cudaGetSymbolAddress((void**)&esp, g_es);
    cudaGetSymbolAddress((void**)&edp, g_ed);

    cudaFuncSetAttribute(edge_kernel,
                         cudaFuncAttributeMaxDynamicSharedMemorySize, EDGE_SMEM_BYTES);
    cudaFuncSetAttribute(prep_gemm_kernel,
                         cudaFuncAttributeMaxDynamicSharedMemorySize, PREP_SMEM_BYTES);
    cudaFuncSetAttribute(node_update_kernel,
                         cudaFuncAttributeMaxDynamicSharedMemorySize, NODE_SMEM_BYTES);
    cudaFuncSetAttribute(proj_pool_kernel,
                         cudaFuncAttributeMaxDynamicSharedMemorySize, PROJ_SMEM_BYTES);
    cudaFuncSetAttribute(readout_kernel,
                         cudaFuncAttributeMaxDynamicSharedMemorySize, RO_SMEM_BYTES);

    // ---- one-time per launch: init h, counting-sort edges by dst ----
    init_h_kernel<<<(N * F_DIM + 255) / 256, 256>>>(zptr, emb, h0, N);
    izero_kernel<<<(N + 255) / 256, 256>>>(curp, N);
    hist_kernel<<<(E + 255) / 256, 256>>>(ei, curp, E);
    scan_kernel<<<1, 1024>>>(curp, curp, N);
    scatter_kernel<<<(E + 255) / 256, 256>>>(ei, pos, curp, esp, edp, en2p, E);

    const int nblk = (N + 63) / 64;
    const dim3 prep_grid(nblk, 5, 2);

    float* hc = h0;
    float* hn = h1;
    for (int l = 0; l < L; l++) {
        const float* W1l = W_msg1 + (size_t)l * DIN * DH;
        prep_gemm_kernel<<<prep_grid, 256, PREP_SMEM_BYTES>>>(
            hc, W1l, b_msg1 + (size_t)l * DH, pdp, psp, N);
        zero_kernel<<<(N * FM_DIM + 255) / 256, 256>>>(aggp, N * FM_DIM);
        edge_kernel<<<(E + EPB - 1) / EPB, 256, EDGE_SMEM_BYTES>>>(
            pdp, psp, W1l + (size_t)256 * DH,
            W_msg2 + (size_t)l * DH * FM_DIM, b_msg2 + (size_t)l * FM_DIM,
            esp, edp, en2p, aggp, E);
        node_update_kernel<<<nblk, 256, NODE_SMEM_BYTES>>>(
            hc, aggp,
            W_up1 + (size_t)l * UIN * UH, b_up1 + (size_t)l * UH,
            W_up2 + (size_t)l * UH * F_DIM, b_up2 + (size_t)l * F_DIM,
            hn, N);
        float* t = hc; hc = hn; hn = t;
    }

    zero_kernel<<<(G * HID + 255) / 256, 256>>>(pooledp, G * HID);
    proj_pool_kernel<<<nblk, 256, PROJ_SMEM_BYTES>>>(
        hc, batch, Wp1, bp1, Wp2, bp2, pooledp, N);
    readout_kernel<<<(G + 63) / 64, 256, RO_SMEM_BYTES>>>(
        pooledp, Wr1, br1, Wr2, br2, out, G);
}

// round 10
// speedup vs baseline: 1.2990x; 1.1313x over previous
#include <cuda_runtime.h>
#include <cuda_fp16.h>
#include <cstdint>

#define F_DIM   128
#define FM_DIM  16
#define DIN     257
#define DH      514
#define UIN     144
#define UH      256
#define HID     128
#define T_OUT   12
#define SP      520     // padded row stride for Pd/Ps in HALVES (1040B, 16B-aligned)

#define MAXN 50048
#define MAXE 800000
#define MAXG 1024

// ---------------- scratch (no allocations allowed) ----------------
__device__ __align__(256) float  g_h0[MAXN * F_DIM];
__device__ __align__(256) float  g_h1[MAXN * F_DIM];
__device__ __align__(256) float  g_en2[MAXE];      // norm2, dst-sorted order
__device__ __align__(256) float  g_agg[MAXN * FM_DIM];
__device__ __align__(256) float  g_pooled[MAXG * HID];
__device__ __align__(256) __half g_Pd[MAXN * SP];  // h @ W1[0:128] + b1   (fp16)
__device__ __align__(256) __half g_Ps[MAXN * SP];  // h @ W1[128:256]      (fp16)
__device__ __align__(256) int    g_cur[MAXN];      // scan cursor
__device__ __align__(256) int    g_es[MAXE];       // sorted src
__device__ __align__(256) int    g_ed[MAXE];       // sorted dst

// ---------------- helpers ----------------
__device__ __forceinline__ float swishf(float x) {
    return __fdividef(x, 1.0f + __expf(-x));
}

// 1-MUFU swish: e = ex2(-|x|*log2e) in (0,1], d = 1+e in (1,2],
// rcp(d) via bit-trick seed + 2 Newton steps (FMA only, rel err ~7e-6).
__device__ __forceinline__ float fast_swish(float x) {
    float e;
    asm("ex2.approx.ftz.f32 %0, %1;" : "=f"(e) : "f"(-fabsf(x) * 1.44269504f));
    float d = 1.0f + e;
    float r = __uint_as_float(0x7EF311C3u - __float_as_uint(d));
    r = r * (2.0f - d * r);
    r = r * (2.0f - d * r);
    float s = (x >= 0.0f) ? r : e * r;   // sigmoid(x)
    return x * s;
}

typedef unsigned long long ull;

__device__ __forceinline__ void fma2(ull& d, ull a, ull b) {
    asm("fma.rn.f32x2 %0, %1, %2, %0;" : "+l"(d) : "l"(a), "l"(b));
}
__device__ __forceinline__ ull pack2(float x) {
    ull r;
    asm("mov.b64 %0, {%1, %1};" : "=l"(r) : "f"(x));
    return r;
}
__device__ __forceinline__ void unpack2(ull v, float& lo, float& hi) {
    asm("mov.b64 {%0, %1}, %2;" : "=f"(lo), "=f"(hi) : "l"(v));
}

// ---------------- small kernels ----------------
__global__ void zero_kernel(float* p, int n) {
    int i = blockIdx.x * blockDim.x + threadIdx.x;
    if (i < n) p[i] = 0.0f;
}
__global__ void izero_kernel(int* p, int n) {
    int i = blockIdx.x * blockDim.x + threadIdx.x;
    if (i < n) p[i] = 0;
}

__global__ void init_h_kernel(const void* zptr, const float* __restrict__ emb,
                              float* __restrict__ h, int N) {
    int i = blockIdx.x * blockDim.x + threadIdx.x;
    if (i >= N * F_DIM) return;
    int node = i / F_DIM, f = i % F_DIM;
    const int* z32 = (const int*)zptr;
    bool is64 = (z32[1] == 0) && (z32[3] == 0) && (z32[5] == 0);
    long long zv = is64 ? ((const long long*)zptr)[node] : (long long)z32[node];
    int e = (zv == 1) ? 0 : (int)(zv - 5);
    h[i] = emb[e * F_DIM + f];
}

// ---------------- counting sort of edges by dst ----------------
__global__ void hist_kernel(const int* __restrict__ ei, int* __restrict__ cnt, int E) {
    int e = blockIdx.x * blockDim.x + threadIdx.x;
    if (e < E) atomicAdd(&cnt[ei[E + e]], 1);
}

__global__ void scan_kernel(int* __restrict__ cnt, int* __restrict__ cur, int N) {
    __shared__ int sdata[1024];
    __shared__ int carry_s;
    if (threadIdx.x == 0) carry_s = 0;
    __syncthreads();
    for (int base = 0; base < N; base += 1024) {
        int i = base + threadIdx.x;
        int v = (i < N) ? cnt[i] : 0;
        sdata[threadIdx.x] = v;
        __syncthreads();
        for (int ofs = 1; ofs < 1024; ofs <<= 1) {
            int t = (threadIdx.x >= ofs) ? sdata[threadIdx.x - ofs] : 0;
            __syncthreads();
            sdata[threadIdx.x] += t;
            __syncthreads();
        }
        int excl = sdata[threadIdx.x] - v + carry_s;
        if (i < N) cur[i] = excl;
        __syncthreads();
        if (threadIdx.x == 0) carry_s += sdata[1023];
        __syncthreads();
    }
}

__global__ void scatter_kernel(const int* __restrict__ ei, const float* __restrict__ pos,
                               int* __restrict__ cur,
                               int* __restrict__ es, int* __restrict__ ed,
                               float* __restrict__ en2, int E) {
    int e = blockIdx.x * blockDim.x + threadIdx.x;
    if (e >= E) return;
    int s = ei[e], d = ei[E + e];
    float dx = pos[s * 3 + 0] - pos[d * 3 + 0];
    float dy = pos[s * 3 + 1] - pos[d * 3 + 1];
    float dz = pos[s * 3 + 2] - pos[d * 3 + 2];
    int p = atomicAdd(&cur[d], 1);
    es[p] = s; ed[p] = d;
    en2[p] = dx * dx + dy * dy + dz * dz;
}

// ---------------- per-node pre-GEMM: P = h @ W (+bias), fp16 out ----------
#define PREP_SMEM_BYTES ((64 * 132 + 8 * 132) * 4)

__global__ __launch_bounds__(256)
void prep_gemm_kernel(const float* __restrict__ h, const float* __restrict__ W1,
                      const float* __restrict__ bias,
                      __half* __restrict__ Pd, __half* __restrict__ Ps, int N) {
    extern __shared__ float sm[];
    float* sH = sm;             // 64 x 132
    float* sB = sH + 64 * 132;  // 8 x 132

    const int tid = threadIdx.x;
    const int n0 = blockIdx.x * 64;
    const int c0 = blockIdx.y * 128;
    const int which = blockIdx.z;
    const float* W = W1 + (size_t)which * 128 * DH;
    __half* P = which ? Ps : Pd;

    for (int idx = tid; idx < 64 * 128; idx += 256) {
        int r = idx >> 7, c = idx & 127;
        int node = n0 + r;
        sH[r * 132 + c] = (node < N) ? h[(size_t)node * F_DIM + c] : 0.0f;
    }
    __syncthreads();

    const int ty = tid >> 4, tx = tid & 15;
    const int r0 = ty * 4, ct = tx * 8;

    ull C01[4], C23[4], C45[4], C67[4];
    #pragma unroll
    for (int i = 0; i < 4; i++) { C01[i] = 0; C23[i] = 0; C45[i] = 0; C67[i] = 0; }

    for (int k0 = 0; k0 < 128; k0 += 8) {
        #pragma unroll
        for (int it = 0; it < 4; it++) {
            int t = tid + it * 256;
            int kk = t >> 7, c = t & 127;
            int col = c0 + c;
            sB[kk * 132 + c] = (col < DH) ? W[(size_t)(k0 + kk) * DH + col] : 0.0f;
        }
        __syncthreads();
        #pragma unroll
        for (int kk = 0; kk < 8; kk++) {
            const float* bp = sB + kk * 132 + ct;
            ull b01 = *(const ull*)(bp);
            ull b23 = *(const ull*)(bp + 2);
            ull b45 = *(const ull*)(bp + 4);
            ull b67 = *(const ull*)(bp + 6);
            #pragma unroll
            for (int i = 0; i < 4; i++) {
                ull aa = pack2(sH[(r0 + i) * 132 + k0 + kk]);
                fma2(C01[i], aa, b01); fma2(C23[i], aa, b23);
                fma2(C45[i], aa, b45); fma2(C67[i], aa, b67);
            }
        }
        __syncthreads();
    }

    #pragma unroll
    for (int i = 0; i < 4; i++) {
        int node = n0 + r0 + i;
        if (node >= N) continue;
        float v[8];
        unpack2(C01[i], v[0], v[1]); unpack2(C23[i], v[2], v[3]);
        unpack2(C45[i], v[4], v[5]); unpack2(C67[i], v[6], v[7]);
        int col0 = c0 + ct;
        __half* prow = P + (size_t)node * SP + col0;
        #pragma unroll
        for (int j = 0; j < 8; j++)
            v[j] += (which == 0 && col0 + j < DH) ? bias[col0 + j] : 0.0f;
        if (col0 + 8 <= DH) {
            __half2 h01 = __floats2half2_rn(v[0], v[1]);
            __half2 h23 = __floats2half2_rn(v[2], v[3]);
            __half2 h45 = __floats2half2_rn(v[4], v[5]);
            __half2 h67 = __floats2half2_rn(v[6], v[7]);
            uint4 st;
            st.x = *(unsigned*)&h01; st.y = *(unsigned*)&h23;
            st.z = *(unsigned*)&h45; st.w = *(unsigned*)&h67;
            *(uint4*)prow = st;
        } else {
            #pragma unroll
            for (int j = 0; j < 8; j++)
                if (col0 + j < SP)
                    prow[j] = __float2half_rn((col0 + j < DH) ? v[j] : 0.0f);
        }
    }
}

// ---------------- edge phase: 1 edge/thread, register-resident -----------
// Each thread owns one edge end-to-end: uint4 fp16 gather of Pd[d]/Ps[s],
// hadd2 fuse, swish in registers, fma2 straight into 16 accumulators.
// W2 rows read via broadcast LDS.128 (1 phase). No sA staging, no barriers
// in the mainloop. Slot-wise prefetch hides gather latency behind the GEMM.
#define EDGE_SMEM_BYTES ((516 * 16 + 516) * 4)

__global__ __launch_bounds__(256)
void edge_kernel(const __half* __restrict__ Pd, const __half* __restrict__ Ps,
                 const float* __restrict__ Wn,   // W1 row 256 (norm2 row)
                 const float* __restrict__ W2, const float* __restrict__ b2,
                 const int* __restrict__ es, const int* __restrict__ ed,
                 const float* __restrict__ en2,
                 float* __restrict__ agg, int E) {
    extern __shared__ float sm[];
    float* sW2 = sm;               // 516 x 16 (rows >=514 zero)
    float* sWn = sW2 + 516 * 16;   // 516 (pad zero)

    const int tid = threadIdx.x;
    for (int i = tid; i < 516 * 16; i += 256) {
        int k = i >> 4;
        sW2[i] = (k < DH) ? W2[i] : 0.0f;
    }
    for (int i = tid; i < 516; i += 256)
        sWn[i] = (i < DH) ? Wn[i] : 0.0f;
    __syncthreads();

    const int e = blockIdx.x * 256 + tid;
    const bool act = (e < E);
    int d = 0, s = 0;
    float n2 = 0.0f;
    if (act) { d = ed[e]; s = es[e]; n2 = en2[e]; }
    const __half* pd = Pd + (size_t)d * SP;
    const __half* ps = Ps + (size_t)s * SP;

    ull m[8];
    #pragma unroll
    for (int j = 0; j < 8; j++) m[j] = 0;

    // prefetch chunk 0 (4 slots of 8 halves per array)
    uint4 bpd[4], bps[4];
    #pragma unroll
    for (int j = 0; j < 4; j++) {
        bpd[j] = *(const uint4*)(pd + j * 8);
        bps[j] = *(const uint4*)(ps + j * 8);
    }

    for (int c = 0; c < 16; c++) {
        const int k0 = c * 32;
        #pragma unroll
        for (int j = 0; j < 4; j++) {
            const __half2* ha = (const __half2*)&bpd[j];
            const __half2* hb = (const __half2*)&bps[j];
            float2 f0 = __half22float2(__hadd2(ha[0], hb[0]));
            float2 f1 = __half22float2(__hadd2(ha[1], hb[1]));
            float2 f2 = __half22float2(__hadd2(ha[2], hb[2]));
            float2 f3 = __half22float2(__hadd2(ha[3], hb[3]));
            // refill this slot for the next chunk (covered by GEMM below)
            if (c < 15) {
                bpd[j] = *(const uint4*)(pd + k0 + 32 + j * 8);
                bps[j] = *(const uint4*)(ps + k0 + 32 + j * 8);
            }
            const int kb = k0 + j * 8;
            float4 wl = *(const float4*)(sWn + kb);
            float4 wh = *(const float4*)(sWn + kb + 4);
            float x[8];
            x[0] = fmaf(n2, wl.x, f0.x); x[1] = fmaf(n2, wl.y, f0.y);
            x[2] = fmaf(n2, wl.z, f1.x); x[3] = fmaf(n2, wl.w, f1.y);
            x[4] = fmaf(n2, wh.x, f2.x); x[5] = fmaf(n2, wh.y, f2.y);
            x[6] = fmaf(n2, wh.z, f3.x); x[7] = fmaf(n2, wh.w, f3.y);
            #pragma unroll
            for (int q = 0; q < 8; q++) {
                float sw = fast_swish(x[q]);
                ull aa = pack2(sw);
                const float* wp = sW2 + (kb + q) * 16;
                float4 w0 = *(const float4*)(wp);
                float4 w1 = *(const float4*)(wp + 4);
                float4 w2v = *(const float4*)(wp + 8);
                float4 w3 = *(const float4*)(wp + 12);
                fma2(m[0], aa, *(ull*)&w0);  fma2(m[1], aa, *((ull*)&w0 + 1));
                fma2(m[2], aa, *(ull*)&w1);  fma2(m[3], aa, *((ull*)&w1 + 1));
                fma2(m[4], aa, *(ull*)&w2v); fma2(m[5], aa, *((ull*)&w2v + 1));
                fma2(m[6], aa, *(ull*)&w3);  fma2(m[7], aa, *((ull*)&w3 + 1));
            }
        }
    }

    // tail k = 512..513
    {
        uint2 va = *(const uint2*)(pd + 512);
        uint2 vb = *(const uint2*)(ps + 512);
        __half2 a0 = *(__half2*)&va.x, b0 = *(__half2*)&vb.x;
        float2 f = __half22float2(__hadd2(a0, b0));
        float xt[2];
        xt[0] = fmaf(n2, sWn[512], f.x);
        xt[1] = fmaf(n2, sWn[513], f.y);
        #pragma unroll
        for (int q = 0; q < 2; q++) {
            float sw = fast_swish(xt[q]);
            ull aa = pack2(sw);
            const float* wp = sW2 + (512 + q) * 16;
            float4 w0 = *(const float4*)(wp);
            float4 w1 = *(const float4*)(wp + 4);
            float4 w2v = *(const float4*)(wp + 8);
            float4 w3 = *(const float4*)(wp + 12);
            fma2(m[0], aa, *(ull*)&w0);  fma2(m[1], aa, *((ull*)&w0 + 1));
            fma2(m[2], aa, *(ull*)&w1);  fma2(m[3], aa, *((ull*)&w1 + 1));
            fma2(m[4], aa, *(ull*)&w2v); fma2(m[5], aa, *((ull*)&w2v + 1));
            fma2(m[6], aa, *(ull*)&w3);  fma2(m[7], aa, *((ull*)&w3 + 1));
        }
    }

    // epilogue: swish(m2 + b2) -> atomic scatter
    if (act) {
        float* ap = agg + (size_t)d * FM_DIM;
        #pragma unroll
        for (int j = 0; j < 8; j++) {
            float lo, hi;
            unpack2(m[j], lo, hi);
            atomicAdd(ap + 2 * j,     fast_swish(lo + b2[2 * j]));
            atomicAdd(ap + 2 * j + 1, fast_swish(hi + b2[2 * j + 1]));
        }
    }
}

// ---------------- fused node update ----------------
#define SU_STR 148
#define NODE_SMEM_BYTES ((64 * SU_STR + 64 * 132 + 8 * 132) * 4)

__global__ __launch_bounds__(256)
void node_update_kernel(const float* __restrict__ h,
                        const float* __restrict__ agg,
                        const float* __restrict__ W1, const float* __restrict__ b1,
                        const float* __restrict__ W2, const float* __restrict__ b2,
                        float* __restrict__ hout, int N) {
    extern __shared__ float sm[];
    float* sU  = sm;
    float* sU1 = sU + 64 * SU_STR;
    float* sB  = sU1 + 64 * 132;

    const int tid = threadIdx.x;
    const int n0 = blockIdx.x * 64;

    for (int idx = tid; idx < 64 * UIN; idx += 256) {
        int r = idx / UIN, c = idx % UIN;
        int node = n0 + r;
        float v = 0.0f;
        if (node < N)
            v = (c < FM_DIM) ? agg[(size_t)node * FM_DIM + c]
                             : h[(size_t)node * F_DIM + (c - FM_DIM)];
        sU[r * SU_STR + c] = v;
    }
    __syncthreads();

    const int ty = tid >> 4, tx = tid & 15;
    const int r0 = ty * 4, ct = tx * 8;

    float C2[4][8];
    #pragma unroll
    for (int i = 0; i < 4; i++)
        #pragma unroll
        for (int j = 0; j < 8; j++) C2[i][j] = 0.0f;

    for (int c0 = 0; c0 < UH; c0 += 128) {
        float C1[4][8];
        #pragma unroll
        for (int i = 0; i < 4; i++)
            #pragma unroll
            for (int j = 0; j < 8; j++) C1[i][j] = 0.0f;

        for (int k0 = 0; k0 < UIN; k0 += 8) {
            #pragma unroll
            for (int it = 0; it < 4; it++) {
                int t = tid + it * 256;
                int kk = t >> 7, c = t & 127;
                sB[kk * 132 + c] = W1[(size_t)(k0 + kk) * UH + c0 + c];
            }
            __syncthreads();
            #pragma unroll
            for (int kk = 0; kk < 8; kk++) {
                float4 b0 = *(const float4*)(sB + kk * 132 + ct);
                float4 b1v = *(const float4*)(sB + kk * 132 + ct + 4);
                #pragma unroll
                for (int i = 0; i < 4; i++) {
                    float a = sU[(r0 + i) * SU_STR + k0 + kk];
                    C1[i][0] += a * b0.x; C1[i][1] += a * b0.y;
                    C1[i][2] += a * b0.z; C1[i][3] += a * b0.w;
                    C1[i][4] += a * b1v.x; C1[i][5] += a * b1v.y;
                    C1[i][6] += a * b1v.z; C1[i][7] += a * b1v.w;
                }
            }
            __syncthreads();
        }
        #pragma unroll
        for (int i = 0; i < 4; i++)
            #pragma unroll
            for (int j = 0; j < 8; j++)
                sU1[(r0 + i) * 132 + ct + j] = swishf(C1[i][j] + b1[c0 + ct + j]);
        __syncthreads();

        for (int k0 = 0; k0 < 128; k0 += 8) {
            #pragma unroll
            for (int it = 0; it < 4; it++) {
                int t = tid + it * 256;
                int kk = t >> 7, c = t & 127;
                sB[kk * 132 + c] = W2[(size_t)(c0 + k0 + kk) * F_DIM + c];
            }
            __syncthreads();
            #pragma unroll
            for (int kk = 0; kk < 8; kk++) {
                float4 b0 = *(const float4*)(sB + kk * 132 + ct);
                float4 b1v = *(const float4*)(sB + kk * 132 + ct + 4);
                #pragma unroll
                for (int i = 0; i < 4; i++) {
                    float a = sU1[(r0 + i) * 132 + k0 + kk];
                    C2[i][0] += a * b0.x; C2[i][1] += a * b0.y;
                    C2[i][2] += a * b0.z; C2[i][3] += a * b0.w;
                    C2[i][4] += a * b1v.x; C2[i][5] += a * b1v.y;
                    C2[i][6] += a * b1v.z; C2[i][7] += a * b1v.w;
                }
            }
            __syncthreads();
        }
    }

    #pragma unroll
    for (int i = 0; i < 4; i++) {
        int node = n0 + r0 + i;
        if (node < N) {
            #pragma unroll
            for (int j = 0; j < 8; j++)
                hout[(size_t)node * F_DIM + ct + j] =
                    C2[i][j] + b2[ct + j] + sU[(r0 + i) * SU_STR + FM_DIM + ct + j];
        }
    }
}

// ---------------- projection + sorted-batch pooling ----------------
#define PROJ_SMEM_BYTES ((64 * 132 * 2 + 8 * 132) * 4 + 64 * 4)

__global__ __launch_bounds__(256)
void proj_pool_kernel(const float* __restrict__ h,
                      const int* __restrict__ batch,
                      const float* __restrict__ Wp1, const float* __restrict__ bp1,
                      const float* __restrict__ Wp2, const float* __restrict__ bp2,
                      float* __restrict__ pooled, int N) {
    extern __shared__ float sm[];
    float* sH = sm;
    float* sG = sH + 64 * 132;
    float* sB = sG + 64 * 132;
    int* sBatch = (int*)(sB + 8 * 132);

    const int tid = threadIdx.x;
    const int n0 = blockIdx.x * 64;

    for (int idx = tid; idx < 64 * HID; idx += 256) {
        int r = idx >> 7, c = idx & 127;
        int node = n0 + r;
        sH[r * 132 + c] = (node < N) ? h[(size_t)node * F_DIM + c] : 0.0f;
    }
    if (tid < 64) {
        int node = n0 + tid;
        sBatch[tid] = (node < N) ? batch[node] : -1;
    }
    __syncthreads();

    const int ty = tid >> 4, tx = tid & 15;
    const int r0 = ty * 4, ct = tx * 8;

    float C1[4][8];
    #pragma unroll
    for (int i = 0; i < 4; i++)
        #pragma unroll
        for (int j = 0; j < 8; j++) C1[i][j] = 0.0f;

    for (int k0 = 0; k0 < HID; k0 += 8) {
        #pragma unroll
        for (int it = 0; it < 4; it++) {
            int t = tid + it * 256;
            int kk = t >> 7, c = t & 127;
            sB[kk * 132 + c] = Wp1[(size_t)(k0 + kk) * HID + c];
        }
        __syncthreads();
        #pragma unroll
        for (int kk = 0; kk < 8; kk++) {
            float4 b0 = *(const float4*)(sB + kk * 132 + ct);
            float4 b1v = *(const float4*)(sB + kk * 132 + ct + 4);
            #pragma unroll
            for (int i = 0; i < 4; i++) {
                float a = sH[(r0 + i) * 132 + k0 + kk];
                C1[i][0] += a * b0.x; C1[i][1] += a * b0.y;
                C1[i][2] += a * b0.z; C1[i][3] += a * b0.w;
                C1[i][4] += a * b1v.x; C1[i][5] += a * b1v.y;
                C1[i][6] += a * b1v.z; C1[i][7] += a * b1v.w;
            }
        }
        __syncthreads();
    }
    #pragma unroll
    for (int i = 0; i < 4; i++)
        #pragma unroll
        for (int j = 0; j < 8; j++)
            sG[(r0 + i) * 132 + ct + j] = swishf(C1[i][j] + bp1[ct + j]);
    __syncthreads();

    float C2[4][8];
    #pragma unroll
    for (int i = 0; i < 4; i++)
        #pragma unroll
        for (int j = 0; j < 8; j++) C2[i][j] = 0.0f;

    for (int k0 = 0; k0 < HID; k0 += 8) {
        #pragma unroll
        for (int it = 0; it < 4; it++) {
            int t = tid + it * 256;
            int kk = t >> 7, c = t & 127;
            sB[kk * 132 + c] = Wp2[(size_t)(k0 + kk) * HID + c];
        }
        __syncthreads();
        #pragma unroll
        for (int kk = 0; kk < 8; kk++) {
            float4 b0 = *(const float4*)(sB + kk * 132 + ct);
            float4 b1v = *(const float4*)(sB + kk * 132 + ct + 4);
            #pragma unroll
            for (int i = 0; i < 4; i++) {
                float a = sG[(r0 + i) * 132 + k0 + kk];
                C2[i][0] += a * b0.x; C2[i][1] += a * b0.y;
                C2[i][2] += a * b0.z; C2[i][3] += a * b0.w;
                C2[i][4] += a * b1v.x; C2[i][5] += a * b1v.y;
                C2[i][6] += a * b1v.z; C2[i][7] += a * b1v.w;
            }
        }
        __syncthreads();
    }
    #pragma unroll
    for (int i = 0; i < 4; i++)
        #pragma unroll
        for (int j = 0; j < 8; j++)
            sH[(r0 + i) * 132 + ct + j] = C2[i][j] + bp2[ct + j];
    __syncthreads();

    if (tid < HID) {
        int col = tid;
        int g = sBatch[0];
        float acc = 0.0f;
        for (int r = 0; r < 64; r++) {
            int gg = sBatch[r];
            if (gg != g) {
                if (g >= 0) atomicAdd(&pooled[(size_t)g * HID + col], acc);
                acc = 0.0f;
                g = gg;
            }
            acc += sH[r * 132 + col];
        }
        if (g >= 0) atomicAdd(&pooled[(size_t)g * HID + col], acc);
    }
}

// ---------------- readout ----------------
#define RO_SMEM_BYTES ((64 * 132 * 2 + 8 * 132) * 4)

__global__ __launch_bounds__(256)
void readout_kernel(const float* __restrict__ pooled,
                    const float* __restrict__ Wr1, const float* __restrict__ br1,
                    const float* __restrict__ Wr2, const float* __restrict__ br2,
                    float* __restrict__ out, int G) {
    extern __shared__ float sm[];
    float* sP = sm;
    float* sR = sP + 64 * 132;
    float* sB = sR + 64 * 132;

    const int tid = threadIdx.x;
    const int g0 = blockIdx.x * 64;

    for (int idx = tid; idx < 64 * HID; idx += 256) {
        int r = idx >> 7, c = idx & 127;
        int g = g0 + r;
        sP[r * 132 + c] = (g < G) ? pooled[(size_t)g * HID + c] : 0.0f;
    }
    __syncthreads();

    const int ty = tid >> 4, tx = tid & 15;
    const int r0 = ty * 4, ct = tx * 8;

    float C1[4][8];
    #pragma unroll
    for (int i = 0; i < 4; i++)
        #pragma unroll
        for (int j = 0; j < 8; j++) C1[i][j] = 0.0f;

    for (int k0 = 0; k0 < HID; k0 += 8) {
        #pragma unroll
        for (int it = 0; it < 4; it++) {
            int t = tid + it * 256;
            int kk = t >> 7, c = t & 127;
            sB[kk * 132 + c] = Wr1[(size_t)(k0 + kk) * HID + c];
        }
        __syncthreads();
        #pragma unroll
        for (int kk = 0; kk < 8; kk++) {
            float4 b0 = *(const float4*)(sB + kk * 132 + ct);
            float4 b1v = *(const float4*)(sB + kk * 132 + ct + 4);
            #pragma unroll
            for (int i = 0; i < 4; i++) {
                float a = sP[(r0 + i) * 132 + k0 + kk];
                C1[i][0] += a * b0.x; C1[i][1] += a * b0.y;
                C1[i][2] += a * b0.z; C1[i][3] += a * b0.w;
                C1[i][4] += a * b1v.x; C1[i][5] += a * b1v.y;
                C1[i][6] += a * b1v.z; C1[i][7] += a * b1v.w;
            }
        }
        __syncthreads();
    }
    #pragma unroll
    for (int i = 0; i < 4; i++)
        #pragma unroll
        for (int j = 0; j < 8; j++)
            sR[(r0 + i) * 132 + ct + j] = swishf(C1[i][j] + br1[ct + j]);
    __syncthreads();

    for (int idx = tid; idx < 64 * T_OUT; idx += 256) {
        int e = idx / T_OUT, t = idx % T_OUT;
        int g = g0 + e;
        if (g < G) {
            float acc = br2[t];
            #pragma unroll 4
            for (int k = 0; k < HID; k++)
                acc += sR[e * 132 + k] * Wr2[(size_t)k * T_OUT + t];
            out[(size_t)g * T_OUT + t] = acc;
        }
    }
}

// ---------------- launch ----------------
extern "C" void kernel_launch(void* const* d_in, const int* in_sizes, int n_in,
                              void* d_out, int out_size) {
    const float* pos    = (const float*)d_in[0];
    const void*  zptr   = d_in[1];
    const int*   ei     = (const int*)d_in[2];
    const int*   batch  = (const int*)d_in[3];
    const float* emb    = (const float*)d_in[4];
    const float* W_msg1 = (const float*)d_in[5];
    const float* b_msg1 = (const float*)d_in[6];
    const float* W_msg2 = (const float*)d_in[7];
    const float* b_msg2 = (const float*)d_in[8];
    const float* W_up1  = (const float*)d_in[9];
    const float* b_up1  = (const float*)d_in[10];
    const float* W_up2  = (const float*)d_in[11];
    const float* b_up2  = (const float*)d_in[12];
    const float* Wp1    = (const float*)d_in[13];
    const float* bp1    = (const float*)d_in[14];
    const float* Wp2    = (const float*)d_in[15];
    const float* bp2    = (const float*)d_in[16];
    const float* Wr1    = (const float*)d_in[17];
    const float* br1    = (const float*)d_in[18];
    const float* Wr2    = (const float*)d_in[19];
    const float* br2    = (const float*)d_in[20];
    float* out = (float*)d_out;

    const int N = in_sizes[0] / 3;
    const int E = in_sizes[2] / 2;
    const int L = in_sizes[5] / (DIN * DH);
    const int G = out_size / T_OUT;

    float *h0, *h1, *aggp, *pooledp, *en2p;
    __half *pdp, *psp;
    int *curp, *esp, *edp;
    cudaGetSymbolAddress((void**)&h0, g_h0);
    cudaGetSymbolAddress((void**)&h1, g_h1);
    cudaGetSymbolAddress((void**)&aggp, g_agg);
    cudaGetSymbolAddress((void**)&pooledp, g_pooled);
    cudaGetSymbolAddress((void**)&en2p, g_en2);
    cudaGetSymbolAddress((void**)&pdp, g_Pd);
    cudaGetSymbolAddress((void**)&psp, g_Ps);
    cudaGetSymbolAddress((void**)&curp, g_cur);
    cudaGetSymbolAddress((void**)&esp, g_es);
    cudaGetSymbolAddress((void**)&edp, g_ed);

    cudaFuncSetAttribute(edge_kernel,
                         cudaFuncAttributeMaxDynamicSharedMemorySize, EDGE_SMEM_BYTES);
    cudaFuncSetAttribute(prep_gemm_kernel,
                         cudaFuncAttributeMaxDynamicSharedMemorySize, PREP_SMEM_BYTES);
    cudaFuncSetAttribute(node_update_kernel,
                         cudaFuncAttributeMaxDynamicSharedMemorySize, NODE_SMEM_BYTES);
    cudaFuncSetAttribute(proj_pool_kernel,
                         cudaFuncAttributeMaxDynamicSharedMemorySize, PROJ_SMEM_BYTES);
    cudaFuncSetAttribute(readout_kernel,
                         cudaFuncAttributeMaxDynamicSharedMemorySize, RO_SMEM_BYTES);

    // ---- one-time per launch: init h, counting-sort edges by dst ----
    init_h_kernel<<<(N * F_DIM + 255) / 256, 256>>>(zptr, emb, h0, N);
    izero_kernel<<<(N + 255) / 256, 256>>>(curp, N);
    hist_kernel<<<(E + 255) / 256, 256>>>(ei, curp, E);
    scan_kernel<<<1, 1024>>>(curp, curp, N);
    scatter_kernel<<<(E + 255) / 256, 256>>>(ei, pos, curp, esp, edp, en2p, E);

    const int nblk = (N + 63) / 64;
    const dim3 prep_grid(nblk, 5, 2);

    float* hc = h0;
    float* hn = h1;
    for (int l = 0; l < L; l++) {
        const float* W1l = W_msg1 + (size_t)l * DIN * DH;
        prep_gemm_kernel<<<prep_grid, 256, PREP_SMEM_BYTES>>>(
            hc, W1l, b_msg1 + (size_t)l * DH, pdp, psp, N);
        zero_kernel<<<(N * FM_DIM + 255) / 256, 256>>>(aggp, N * FM_DIM);
        edge_kernel<<<(E + 255) / 256, 256, EDGE_SMEM_BYTES>>>(
            pdp, psp, W1l + (size_t)256 * DH,
            W_msg2 + (size_t)l * DH * FM_DIM, b_msg2 + (size_t)l * FM_DIM,
            esp, edp, en2p, aggp, E);
        node_update_kernel<<<nblk, 256, NODE_SMEM_BYTES>>>(
            hc, aggp,
            W_up1 + (size_t)l * UIN * UH, b_up1 + (size_t)l * UH,
            W_up2 + (size_t)l * UH * F_DIM, b_up2 + (size_t)l * F_DIM,
            hn, N);
        float* t = hc; hc = hn; hn = t;
    }

    zero_kernel<<<(G * HID + 255) / 256, 256>>>(pooledp, G * HID);
    proj_pool_kernel<<<nblk, 256, PROJ_SMEM_BYTES>>>(
        hc, batch, Wp1, bp1, Wp2, bp2, pooledp, N);
    readout_kernel<<<(G + 63) / 64, 256, RO_SMEM_BYTES>>>(
        pooledp, Wr1, br1, Wr2, br2, out, G);
}

// round 12
// speedup vs baseline: 1.3162x; 1.0132x over previous
#include <cuda_runtime.h>
#include <cuda_fp16.h>
#include <cstdint>

#define F_DIM   128
#define FM_DIM  16
#define DIN     257
#define DH      514
#define UIN     144
#define UH      256
#define HID     128
#define T_OUT   12
#define SP      520     // padded row stride for Pd/Ps in HALVES (1040B, 16B-aligned)

#define MAXN 50048
#define MAXE 800000
#define MAXG 1024

// ---------------- scratch (no allocations allowed) ----------------
__device__ __align__(256) float  g_h0[MAXN * F_DIM];
__device__ __align__(256) float  g_h1[MAXN * F_DIM];
__device__ __align__(256) float  g_en2[MAXE];      // norm2, dst-sorted order
__device__ __align__(256) float  g_agg[MAXN * FM_DIM];
__device__ __align__(256) float  g_pooled[MAXG * HID];
__device__ __align__(256) __half g_Pd[MAXN * SP];  // h @ W1[0:128] + b1   (fp16)
__device__ __align__(256) __half g_Ps[MAXN * SP];  // h @ W1[128:256]      (fp16)
__device__ __align__(256) int    g_cur[MAXN];      // scan cursor
__device__ __align__(256) int    g_es[MAXE];       // sorted src
__device__ __align__(256) int    g_ed[MAXE];       // sorted dst

// ---------------- helpers ----------------
__device__ __forceinline__ float swishf(float x) {
    return __fdividef(x, 1.0f + __expf(-x));
}

typedef unsigned long long ull;

__device__ __forceinline__ void fma2(ull& d, ull a, ull b) {
    asm("fma.rn.f32x2 %0, %1, %2, %0;" : "+l"(d) : "l"(a), "l"(b));
}
__device__ __forceinline__ ull pack2(float x) {
    ull r;
    asm("mov.b64 %0, {%1, %1};" : "=l"(r) : "f"(x));
    return r;
}
__device__ __forceinline__ void unpack2(ull v, float& lo, float& hi) {
    asm("mov.b64 {%0, %1}, %2;" : "=f"(lo), "=f"(hi) : "l"(v));
}

// ---------------- small kernels ----------------
__global__ void zero_kernel(float* p, int n) {
    int i = blockIdx.x * blockDim.x + threadIdx.x;
    if (i < n) p[i] = 0.0f;
}
__global__ void izero_kernel(int* p, int n) {
    int i = blockIdx.x * blockDim.x + threadIdx.x;
    if (i < n) p[i] = 0;
}

__global__ void init_h_kernel(const void* zptr, const float* __restrict__ emb,
                              float* __restrict__ h, int N) {
    int i = blockIdx.x * blockDim.x + threadIdx.x;
    if (i >= N * F_DIM) return;
    int node = i / F_DIM, f = i % F_DIM;
    const int* z32 = (const int*)zptr;
    bool is64 = (z32[1] == 0) && (z32[3] == 0) && (z32[5] == 0);
    long long zv = is64 ? ((const long long*)zptr)[node] : (long long)z32[node];
    int e = (zv == 1) ? 0 : (int)(zv - 5);
    h[i] = emb[e * F_DIM + f];
}

// ---------------- counting sort of edges by dst ----------------
__global__ void hist_kernel(const int* __restrict__ ei, int* __restrict__ cnt, int E) {
    int e = blockIdx.x * blockDim.x + threadIdx.x;
    if (e < E) atomicAdd(&cnt[ei[E + e]], 1);
}

__global__ void scan_kernel(int* __restrict__ cnt, int* __restrict__ cur, int N) {
    __shared__ int sdata[1024];
    __shared__ int carry_s;
    if (threadIdx.x == 0) carry_s = 0;
    __syncthreads();
    for (int base = 0; base < N; base += 1024) {
        int i = base + threadIdx.x;
        int v = (i < N) ? cnt[i] : 0;
        sdata[threadIdx.x] = v;
        __syncthreads();
        for (int ofs = 1; ofs < 1024; ofs <<= 1) {
            int t = (threadIdx.x >= ofs) ? sdata[threadIdx.x - ofs] : 0;
            __syncthreads();
            sdata[threadIdx.x] += t;
            __syncthreads();
        }
        int excl = sdata[threadIdx.x] - v + carry_s;
        if (i < N) cur[i] = excl;
        __syncthreads();
        if (threadIdx.x == 0) carry_s += sdata[1023];
        __syncthreads();
    }
}

__global__ void scatter_kernel(const int* __restrict__ ei, const float* __restrict__ pos,
                               int* __restrict__ cur,
                               int* __restrict__ es, int* __restrict__ ed,
                               float* __restrict__ en2, int E) {
    int e = blockIdx.x * blockDim.x + threadIdx.x;
    if (e >= E) return;
    int s = ei[e], d = ei[E + e];
    float dx = pos[s * 3 + 0] - pos[d * 3 + 0];
    float dy = pos[s * 3 + 1] - pos[d * 3 + 1];
    float dz = pos[s * 3 + 2] - pos[d * 3 + 2];
    int p = atomicAdd(&cur[d], 1);
    es[p] = s; ed[p] = d;
    en2[p] = dx * dx + dy * dy + dz * dz;
}

// ---------------- per-node pre-GEMM: P = h @ W (+bias), fp16 out ----------
// 128-node x 128-col tile, 8x8 output per thread (f32x2), 2 CTA/SM.
#define PREP_SMEM_BYTES ((128 * 132 + 8 * 132) * 4)

__global__ __launch_bounds__(256)
void prep_gemm_kernel(const float* __restrict__ h, const float* __restrict__ W1,
                      const float* __restrict__ bias,
                      __half* __restrict__ Pd, __half* __restrict__ Ps, int N) {
    extern __shared__ float sm[];
    float* sH = sm;              // 128 x 132
    float* sB = sH + 128 * 132;  // 8 x 132

    const int tid = threadIdx.x;
    const int n0 = blockIdx.x * 128;
    const int c0 = blockIdx.y * 128;
    const int which = blockIdx.z;
    const float* W = W1 + (size_t)which * 128 * DH;
    __half* P = which ? Ps : Pd;

    // load h tile [128 x 128] as float4
    for (int idx = tid; idx < 128 * 32; idx += 256) {
        int r = idx >> 5, c4 = (idx & 31) * 4;
        int node = n0 + r;
        float4 v = make_float4(0.f, 0.f, 0.f, 0.f);
        if (node < N) v = *(const float4*)(h + (size_t)node * F_DIM + c4);
        *(float4*)(sH + r * 132 + c4) = v;
    }
    __syncthreads();

    const int ty = tid >> 4, tx = tid & 15;
    const int r0 = ty * 8, ct = tx * 8;

    ull C[8][4];
    #pragma unroll
    for (int i = 0; i < 8; i++)
        #pragma unroll
        for (int j = 0; j < 4; j++) C[i][j] = 0;

    for (int k0 = 0; k0 < 128; k0 += 8) {
        #pragma unroll
        for (int it = 0; it < 4; it++) {
            int t = tid + it * 256;
            int kk = t >> 7, c = t & 127;
            int col = c0 + c;
            sB[kk * 132 + c] = (col < DH) ? W[(size_t)(k0 + kk) * DH + col] : 0.0f;
        }
        __syncthreads();
        #pragma unroll
        for (int kk = 0; kk < 8; kk++) {
            const float* bp = sB + kk * 132 + ct;
            ull b0 = *(const ull*)(bp);
            ull b1 = *(const ull*)(bp + 2);
            ull b2v = *(const ull*)(bp + 4);
            ull b3 = *(const ull*)(bp + 6);
            #pragma unroll
            for (int i = 0; i < 8; i++) {
                ull aa = pack2(sH[(r0 + i) * 132 + k0 + kk]);
                fma2(C[i][0], aa, b0); fma2(C[i][1], aa, b1);
                fma2(C[i][2], aa, b2v); fma2(C[i][3], aa, b3);
            }
        }
        __syncthreads();
    }

    #pragma unroll
    for (int i = 0; i < 8; i++) {
        int node = n0 + r0 + i;
        if (node >= N) continue;
        float v[8];
        unpack2(C[i][0], v[0], v[1]); unpack2(C[i][1], v[2], v[3]);
        unpack2(C[i][2], v[4], v[5]); unpack2(C[i][3], v[6], v[7]);
        int col0 = c0 + ct;
        __half* prow = P + (size_t)node * SP + col0;
        #pragma unroll
        for (int j = 0; j < 8; j++)
            v[j] += (which == 0 && col0 + j < DH) ? bias[col0 + j] : 0.0f;
        if (col0 + 8 <= DH) {
            __half2 h01 = __floats2half2_rn(v[0], v[1]);
            __half2 h23 = __floats2half2_rn(v[2], v[3]);
            __half2 h45 = __floats2half2_rn(v[4], v[5]);
            __half2 h67 = __floats2half2_rn(v[6], v[7]);
            uint4 st;
            st.x = *(unsigned*)&h01; st.y = *(unsigned*)&h23;
            st.z = *(unsigned*)&h45; st.w = *(unsigned*)&h67;
            *(uint4*)prow = st;
        } else {
            #pragma unroll
            for (int j = 0; j < 8; j++)
                if (col0 + j < SP)
                    prow[j] = __float2half_rn((col0 + j < DH) ? v[j] : 0.0f);
        }
    }
}

// ---------------- edge phase: 1 edge/thread, register-resident -----------
#define EDGE_SMEM_BYTES ((516 * 16 + 516) * 4)

__global__ __launch_bounds__(256)
void edge_kernel(const __half* __restrict__ Pd, const __half* __restrict__ Ps,
                 const float* __restrict__ Wn,   // W1 row 256 (norm2 row)
                 const float* __restrict__ W2, const float* __restrict__ b2,
                 const int* __restrict__ es, const int* __restrict__ ed,
                 const float* __restrict__ en2,
                 float* __restrict__ agg, int E) {
    extern __shared__ float sm[];
    float* sW2 = sm;               // 516 x 16 (rows >=514 zero)
    float* sWn = sW2 + 516 * 16;   // 516 (pad zero)

    const int tid = threadIdx.x;
    for (int i = tid; i < 516 * 16; i += 256) {
        int k = i >> 4;
        sW2[i] = (k < DH) ? W2[i] : 0.0f;
    }
    for (int i = tid; i < 516; i += 256)
        sWn[i] = (i < DH) ? Wn[i] : 0.0f;
    __syncthreads();

    const int e = blockIdx.x * 256 + tid;
    const bool act = (e < E);
    int d = 0, s = 0;
    float n2 = 0.0f;
    if (act) { d = ed[e]; s = es[e]; n2 = en2[e]; }
    const __half* pd = Pd + (size_t)d * SP;
    const __half* ps = Ps + (size_t)s * SP;

    ull m[8];
    #pragma unroll
    for (int j = 0; j < 8; j++) m[j] = 0;

    // prefetch chunk 0 (4 slots of 8 halves per array)
    uint4 bpd[4], bps[4];
    #pragma unroll
    for (int j = 0; j < 4; j++) {
        bpd[j] = *(const uint4*)(pd + j * 8);
        bps[j] = *(const uint4*)(ps + j * 8);
    }

    for (int c = 0; c < 16; c++) {
        const int k0 = c * 32;
        #pragma unroll
        for (int j = 0; j < 4; j++) {
            const __half2* ha = (const __half2*)&bpd[j];
            const __half2* hb = (const __half2*)&bps[j];
            float2 f0 = __half22float2(__hadd2(ha[0], hb[0]));
            float2 f1 = __half22float2(__hadd2(ha[1], hb[1]));
            float2 f2 = __half22float2(__hadd2(ha[2], hb[2]));
            float2 f3 = __half22float2(__hadd2(ha[3], hb[3]));
            // refill this slot for the next chunk (covered by GEMM below)
            if (c < 15) {
                bpd[j] = *(const uint4*)(pd + k0 + 32 + j * 8);
                bps[j] = *(const uint4*)(ps + k0 + 32 + j * 8);
            }
            const int kb = k0 + j * 8;
            float4 wl = *(const float4*)(sWn + kb);
            float4 wh = *(const float4*)(sWn + kb + 4);
            float x[8];
            x[0] = fmaf(n2, wl.x, f0.x); x[1] = fmaf(n2, wl.y, f0.y);
            x[2] = fmaf(n2, wl.z, f1.x); x[3] = fmaf(n2, wl.w, f1.y);
            x[4] = fmaf(n2, wh.x, f2.x); x[5] = fmaf(n2, wh.y, f2.y);
            x[6] = fmaf(n2, wh.z, f3.x); x[7] = fmaf(n2, wh.w, f3.y);
            #pragma unroll
            for (int q = 0; q < 8; q++) {
                float sw = swishf(x[q]);
                ull aa = pack2(sw);
                const float* wp = sW2 + (kb + q) * 16;
                float4 w0 = *(const float4*)(wp);
                float4 w1 = *(const float4*)(wp + 4);
                float4 w2v = *(const float4*)(wp + 8);
                float4 w3 = *(const float4*)(wp + 12);
                fma2(m[0], aa, *(ull*)&w0);  fma2(m[1], aa, *((ull*)&w0 + 1));
                fma2(m[2], aa, *(ull*)&w1);  fma2(m[3], aa, *((ull*)&w1 + 1));
                fma2(m[4], aa, *(ull*)&w2v); fma2(m[5], aa, *((ull*)&w2v + 1));
                fma2(m[6], aa, *(ull*)&w3);  fma2(m[7], aa, *((ull*)&w3 + 1));
            }
        }
    }

    // tail k = 512..513
    {
        uint2 va = *(const uint2*)(pd + 512);
        uint2 vb = *(const uint2*)(ps + 512);
        __half2 a0 = *(__half2*)&va.x, b0 = *(__half2*)&vb.x;
        float2 f = __half22float2(__hadd2(a0, b0));
        float xt[2];
        xt[0] = fmaf(n2, sWn[512], f.x);
        xt[1] = fmaf(n2, sWn[513], f.y);
        #pragma unroll
        for (int q = 0; q < 2; q++) {
            float sw = swishf(xt[q]);
            ull aa = pack2(sw);
            const float* wp = sW2 + (512 + q) * 16;
            float4 w0 = *(const float4*)(wp);
            float4 w1 = *(const float4*)(wp + 4);
            float4 w2v = *(const float4*)(wp + 8);
            float4 w3 = *(const float4*)(wp + 12);
            fma2(m[0], aa, *(ull*)&w0);  fma2(m[1], aa, *((ull*)&w0 + 1));
            fma2(m[2], aa, *(ull*)&w1);  fma2(m[3], aa, *((ull*)&w1 + 1));
            fma2(m[4], aa, *(ull*)&w2v); fma2(m[5], aa, *((ull*)&w2v + 1));
            fma2(m[6], aa, *(ull*)&w3);  fma2(m[7], aa, *((ull*)&w3 + 1));
        }
    }

    // epilogue: swish(m2 + b2) -> atomic scatter
    if (act) {
        float* ap = agg + (size_t)d * FM_DIM;
        #pragma unroll
        for (int j = 0; j < 8; j++) {
            float lo, hi;
            unpack2(m[j], lo, hi);
            atomicAdd(ap + 2 * j,     swishf(lo + b2[2 * j]));
            atomicAdd(ap + 2 * j + 1, swishf(hi + b2[2 * j + 1]));
        }
    }
}

// ---------------- fused node update ----------------
#define SU_STR 148
#define NODE_SMEM_BYTES ((64 * SU_STR + 64 * 132 + 8 * 132) * 4)

__global__ __launch_bounds__(256)
void node_update_kernel(const float* __restrict__ h,
                        const float* __restrict__ agg,
                        const float* __restrict__ W1, const float* __restrict__ b1,
                        const float* __restrict__ W2, const float* __restrict__ b2,
                        float* __restrict__ hout, int N) {
    extern __shared__ float sm[];
    float* sU  = sm;
    float* sU1 = sU + 64 * SU_STR;
    float* sB  = sU1 + 64 * 132;

    const int tid = threadIdx.x;
    const int n0 = blockIdx.x * 64;

    for (int idx = tid; idx < 64 * UIN; idx += 256) {
        int r = idx / UIN, c = idx % UIN;
        int node = n0 + r;
        float v = 0.0f;
        if (node < N)
            v = (c < FM_DIM) ? agg[(size_t)node * FM_DIM + c]
                             : h[(size_t)node * F_DIM + (c - FM_DIM)];
        sU[r * SU_STR + c] = v;
    }
    __syncthreads();

    const int ty = tid >> 4, tx = tid & 15;
    const int r0 = ty * 4, ct = tx * 8;

    float C2[4][8];
    #pragma unroll
    for (int i = 0; i < 4; i++)
        #pragma unroll
        for (int j = 0; j < 8; j++) C2[i][j] = 0.0f;

    for (int c0 = 0; c0 < UH; c0 += 128) {
        float C1[4][8];
        #pragma unroll
        for (int i = 0; i < 4; i++)
            #pragma unroll
            for (int j = 0; j < 8; j++) C1[i][j] = 0.0f;

        for (int k0 = 0; k0 < UIN; k0 += 8) {
            #pragma unroll
            for (int it = 0; it < 4; it++) {
                int t = tid + it * 256;
                int kk = t >> 7, c = t & 127;
                sB[kk * 132 + c] = W1[(size_t)(k0 + kk) * UH + c0 + c];
            }
            __syncthreads();
            #pragma unroll
            for (int kk = 0; kk < 8; kk++) {
                float4 b0 = *(const float4*)(sB + kk * 132 + ct);
                float4 b1v = *(const float4*)(sB + kk * 132 + ct + 4);
                #pragma unroll
                for (int i = 0; i < 4; i++) {
                    float a = sU[(r0 + i) * SU_STR + k0 + kk];
                    C1[i][0] += a * b0.x; C1[i][1] += a * b0.y;
                    C1[i][2] += a * b0.z; C1[i][3] += a * b0.w;
                    C1[i][4] += a * b1v.x; C1[i][5] += a * b1v.y;
                    C1[i][6] += a * b1v.z; C1[i][7] += a * b1v.w;
                }
            }
            __syncthreads();
        }
        #pragma unroll
        for (int i = 0; i < 4; i++)
            #pragma unroll
            for (int j = 0; j < 8; j++)
                sU1[(r0 + i) * 132 + ct + j] = swishf(C1[i][j] + b1[c0 + ct + j]);
        __syncthreads();

        for (int k0 = 0; k0 < 128; k0 += 8) {
            #pragma unroll
            for (int it = 0; it < 4; it++) {
                int t = tid + it * 256;
                int kk = t >> 7, c = t & 127;
                sB[kk * 132 + c] = W2[(size_t)(c0 + k0 + kk) * F_DIM + c];
            }
            __syncthreads();
            #pragma unroll
            for (int kk = 0; kk < 8; kk++) {
                float4 b0 = *(const float4*)(sB + kk * 132 + ct);
                float4 b1v = *(const float4*)(sB + kk * 132 + ct + 4);
                #pragma unroll
                for (int i = 0; i < 4; i++) {
                    float a = sU1[(r0 + i) * 132 + k0 + kk];
                    C2[i][0] += a * b0.x; C2[i][1] += a * b0.y;
                    C2[i][2] += a * b0.z; C2[i][3] += a * b0.w;
                    C2[i][4] += a * b1v.x; C2[i][5] += a * b1v.y;
                    C2[i][6] += a * b1v.z; C2[i][7] += a * b1v.w;
                }
            }
            __syncthreads();
        }
    }

    #pragma unroll
    for (int i = 0; i < 4; i++) {
        int node = n0 + r0 + i;
        if (node < N) {
            #pragma unroll
            for (int j = 0; j < 8; j++)
                hout[(size_t)node * F_DIM + ct + j] =
                    C2[i][j] + b2[ct + j] + sU[(r0 + i) * SU_STR + FM_DIM + ct + j];
        }
    }
}

// ---------------- projection + sorted-batch pooling ----------------
#define PROJ_SMEM_BYTES ((64 * 132 * 2 + 8 * 132) * 4 + 64 * 4)

__global__ __launch_bounds__(256)
void proj_pool_kernel(const float* __restrict__ h,
                      const int* __restrict__ batch,
                      const float* __restrict__ Wp1, const float* __restrict__ bp1,
                      const float* __restrict__ Wp2, const float* __restrict__ bp2,
                      float* __restrict__ pooled, int N) {
    extern __shared__ float sm[];
    float* sH = sm;
    float* sG = sH + 64 * 132;
    float* sB = sG + 64 * 132;
    int* sBatch = (int*)(sB + 8 * 132);

    const int tid = threadIdx.x;
    const int n0 = blockIdx.x * 64;

    for (int idx = tid; idx < 64 * HID; idx += 256) {
        int r = idx >> 7, c = idx & 127;
        int node = n0 + r;
        sH[r * 132 + c] = (node < N) ? h[(size_t)node * F_DIM + c] : 0.0f;
    }
    if (tid < 64) {
        int node = n0 + tid;
        sBatch[tid] = (node < N) ? batch[node] : -1;
    }
    __syncthreads();

    const int ty = tid >> 4, tx = tid & 15;
    const int r0 = ty * 4, ct = tx * 8;

    float C1[4][8];
    #pragma unroll
    for (int i = 0; i < 4; i++)
        #pragma unroll
        for (int j = 0; j < 8; j++) C1[i][j] = 0.0f;

    for (int k0 = 0; k0 < HID; k0 += 8) {
        #pragma unroll
        for (int it = 0; it < 4; it++) {
            int t = tid + it * 256;
            int kk = t >> 7, c = t & 127;
            sB[kk * 132 + c] = Wp1[(size_t)(k0 + kk) * HID + c];
        }
        __syncthreads();
        #pragma unroll
        for (int kk = 0; kk < 8; kk++) {
            float4 b0 = *(const float4*)(sB + kk * 132 + ct);
            float4 b1v = *(const float4*)(sB + kk * 132 + ct + 4);
            #pragma unroll
            for (int i = 0; i < 4; i++) {
                float a = sH[(r0 + i) * 132 + k0 + kk];
                C1[i][0] += a * b0.x; C1[i][1] += a * b0.y;
                C1[i][2] += a * b0.z; C1[i][3] += a * b0.w;
                C1[i][4] += a * b1v.x; C1[i][5] += a * b1v.y;
                C1[i][6] += a * b1v.z; C1[i][7] += a * b1v.w;
            }
        }
        __syncthreads();
    }
    #pragma unroll
    for (int i = 0; i < 4; i++)
        #pragma unroll
        for (int j = 0; j < 8; j++)
            sG[(r0 + i) * 132 + ct + j] = swishf(C1[i][j] + bp1[ct + j]);
    __syncthreads();

    float C2[4][8];
    #pragma unroll
    for (int i = 0; i < 4; i++)
        #pragma unroll
        for (int j = 0; j < 8; j++) C2[i][j] = 0.0f;

    for (int k0 = 0; k0 < HID; k0 += 8) {
        #pragma unroll
        for (int it = 0; it < 4; it++) {
            int t = tid + it * 256;
            int kk = t >> 7, c = t & 127;
            sB[kk * 132 + c] = Wp2[(size_t)(k0 + kk) * HID + c];
        }
        __syncthreads();
        #pragma unroll
        for (int kk = 0; kk < 8; kk++) {
            float4 b0 = *(const float4*)(sB + kk * 132 + ct);
            float4 b1v = *(const float4*)(sB + kk * 132 + ct + 4);
            #pragma unroll
            for (int i = 0; i < 4; i++) {
                float a = sG[(r0 + i) * 132 + k0 + kk];
                C2[i][0] += a * b0.x; C2[i][1] += a * b0.y;
                C2[i][2] += a * b0.z; C2[i][3] += a * b0.w;
                C2[i][4] += a * b1v.x; C2[i][5] += a * b1v.y;
                C2[i][6] += a * b1v.z; C2[i][7] += a * b1v.w;
            }
        }
        __syncthreads();
    }
    #pragma unroll
    for (int i = 0; i < 4; i++)
        #pragma unroll
        for (int j = 0; j < 8; j++)
            sH[(r0 + i) * 132 + ct + j] = C2[i][j] + bp2[ct + j];
    __syncthreads();

    if (tid < HID) {
        int col = tid;
        int g = sBatch[0];
        float acc = 0.0f;
        for (int r = 0; r < 64; r++) {
            int gg = sBatch[r];
            if (gg != g) {
                if (g >= 0) atomicAdd(&pooled[(size_t)g * HID + col], acc);
                acc = 0.0f;
                g = gg;
            }
            acc += sH[r * 132 + col];
        }
        if (g >= 0) atomicAdd(&pooled[(size_t)g * HID + col], acc);
    }
}

// ---------------- readout ----------------
#define RO_SMEM_BYTES ((64 * 132 * 2 + 8 * 132) * 4)

__global__ __launch_bounds__(256)
void readout_kernel(const float* __restrict__ pooled,
                    const float* __restrict__ Wr1, const float* __restrict__ br1,
                    const float* __restrict__ Wr2, const float* __restrict__ br2,
                    float* __restrict__ out, int G) {
    extern __shared__ float sm[];
    float* sP = sm;
    float* sR = sP + 64 * 132;
    float* sB = sR + 64 * 132;

    const int tid = threadIdx.x;
    const int g0 = blockIdx.x * 64;

    for (int idx = tid; idx < 64 * HID; idx += 256) {
        int r = idx >> 7, c = idx & 127;
        int g = g0 + r;
        sP[r * 132 + c] = (g < G) ? pooled[(size_t)g * HID + c] : 0.0f;
    }
    __syncthreads();

    const int ty = tid >> 4, tx = tid & 15;
    const int r0 = ty * 4, ct = tx * 8;

    float C1[4][8];
    #pragma unroll
    for (int i = 0; i < 4; i++)
        #pragma unroll
        for (int j = 0; j < 8; j++) C1[i][j] = 0.0f;

    for (int k0 = 0; k0 < HID; k0 += 8) {
        #pragma unroll
        for (int it = 0; it < 4; it++) {
            int t = tid + it * 256;
            int kk = t >> 7, c = t & 127;
            sB[kk * 132 + c] = Wr1[(size_t)(k0 + kk) * HID + c];
        }
        __syncthreads();
        #pragma unroll
        for (int kk = 0; kk < 8; kk++) {
            float4 b0 = *(const float4*)(sB + kk * 132 + ct);
            float4 b1v = *(const float4*)(sB + kk * 132 + ct + 4);
            #pragma unroll
            for (int i = 0; i < 4; i++) {
                float a = sP[(r0 + i) * 132 + k0 + kk];
                C1[i][0] += a * b0.x; C1[i][1] += a * b0.y;
                C1[i][2] += a * b0.z; C1[i][3] += a * b0.w;
                C1[i][4] += a * b1v.x; C1[i][5] += a * b1v.y;
                C1[i][6] += a * b1v.z; C1[i][7] += a * b1v.w;
            }
        }
        __syncthreads();
    }
    #pragma unroll
    for (int i = 0; i < 4; i++)
        #pragma unroll
        for (int j = 0; j < 8; j++)
            sR[(r0 + i) * 132 + ct + j] = swishf(C1[i][j] + br1[ct + j]);
    __syncthreads();

    for (int idx = tid; idx < 64 * T_OUT; idx += 256) {
        int e = idx / T_OUT, t = idx % T_OUT;
        int g = g0 + e;
        if (g < G) {
            float acc = br2[t];
            #pragma unroll 4
            for (int k = 0; k < HID; k++)
                acc += sR[e * 132 + k] * Wr2[(size_t)k * T_OUT + t];
            out[(size_t)g * T_OUT + t] = acc;
        }
    }
}

// ---------------- launch ----------------
extern "C" void kernel_launch(void* const* d_in, const int* in_sizes, int n_in,
                              void* d_out, int out_size) {
    const float* pos    = (const float*)d_in[0];
    const void*  zptr   = d_in[1];
    const int*   ei     = (const int*)d_in[2];
    const int*   batch  = (const int*)d_in[3];
    const float* emb    = (const float*)d_in[4];
    const float* W_msg1 = (const float*)d_in[5];
    const float* b_msg1 = (const float*)d_in[6];
    const float* W_msg2 = (const float*)d_in[7];
    const float* b_msg2 = (const float*)d_in[8];
    const float* W_up1  = (const float*)d_in[9];
    const float* b_up1  = (const float*)d_in[10];
    const float* W_up2  = (const float*)d_in[11];
    const float* b_up2  = (const float*)d_in[12];
    const float* Wp1    = (const float*)d_in[13];
    const float* bp1    = (const float*)d_in[14];
    const float* Wp2    = (const float*)d_in[15];
    const float* bp2    = (const float*)d_in[16];
    const float* Wr1    = (const float*)d_in[17];
    const float* br1    = (const float*)d_in[18];
    const float* Wr2    = (const float*)d_in[19];
    const float* br2    = (const float*)d_in[20];
    float* out = (float*)d_out;

    const int N = in_sizes[0] / 3;
    const int E = in_sizes[2] / 2;
    const int L = in_sizes[5] / (DIN * DH);
    const int G = out_size / T_OUT;

    float *h0, *h1, *aggp, *pooledp, *en2p;
    __half *pdp, *psp;
    int *curp, *esp, *edp;
    cudaGetSymbolAddress((void**)&h0, g_h0);
    cudaGetSymbolAddress((void**)&h1, g_h1);
    cudaGetSymbolAddress((void**)&aggp, g_agg);
    cudaGetSymbolAddress((void**)&pooledp, g_pooled);
    cudaGetSymbolAddress((void**)&en2p, g_en2);
    cudaGetSymbolAddress((void**)&pdp, g_Pd);
    cudaGetSymbolAddress((void**)&psp, g_Ps);
    cudaGetSymbolAddress((void**)&curp, g_cur);
    cudaGetSymbolAddress((void**)&esp, g_es);
    cudaGetSymbolAddress((void**)&edp, g_ed);

    cudaFuncSetAttribute(edge_kernel,
                         cudaFuncAttributeMaxDynamicSharedMemorySize, EDGE_SMEM_BYTES);
    cudaFuncSetAttribute(prep_gemm_kernel,
                         cudaFuncAttributeMaxDynamicSharedMemorySize, PREP_SMEM_BYTES);
    cudaFuncSetAttribute(node_update_kernel,
                         cudaFuncAttributeMaxDynamicSharedMemorySize, NODE_SMEM_BYTES);
    cudaFuncSetAttribute(proj_pool_kernel,
                         cudaFuncAttributeMaxDynamicSharedMemorySize, PROJ_SMEM_BYTES);
    cudaFuncSetAttribute(readout_kernel,
                         cudaFuncAttributeMaxDynamicSharedMemorySize, RO_SMEM_BYTES);

    // ---- one-time per launch: init h, counting-sort edges by dst ----
    init_h_kernel<<<(N * F_DIM + 255) / 256, 256>>>(zptr, emb, h0, N);
    izero_kernel<<<(N + 255) / 256, 256>>>(curp, N);
    hist_kernel<<<(E + 255) / 256, 256>>>(ei, curp, E);
    scan_kernel<<<1, 1024>>>(curp, curp, N);
    scatter_kernel<<<(E + 255) / 256, 256>>>(ei, pos, curp, esp, edp, en2p, E);

    const int nblk = (N + 63) / 64;
    const dim3 prep_grid((N + 127) / 128, 5, 2);

    float* hc = h0;
    float* hn = h1;
    for (int l = 0; l < L; l++) {
        const float* W1l = W_msg1 + (size_t)l * DIN * DH;
        prep_gemm_kernel<<<prep_grid, 256, PREP_SMEM_BYTES>>>(
            hc, W1l, b_msg1 + (size_t)l * DH, pdp, psp, N);
        zero_kernel<<<(N * FM_DIM + 255) / 256, 256>>>(aggp, N * FM_DIM);
        edge_kernel<<<(E + 255) / 256, 256, EDGE_SMEM_BYTES>>>(
            pdp, psp, W1l + (size_t)256 * DH,
            W_msg2 + (size_t)l * DH * FM_DIM, b_msg2 + (size_t)l * FM_DIM,
            esp, edp, en2p, aggp, E);
        node_update_kernel<<<nblk, 256, NODE_SMEM_BYTES>>>(
            hc, aggp,
            W_up1 + (size_t)l * UIN * UH, b_up1 + (size_t)l * UH,
            W_up2 + (size_t)l * UH * F_DIM, b_up2 + (size_t)l * F_DIM,
            hn, N);
        float* t = hc; hc = hn; hn = t;
    }

    zero_kernel<<<(G * HID + 255) / 256, 256>>>(pooledp, G * HID);
    proj_pool_kernel<<<nblk, 256, PROJ_SMEM_BYTES>>>(
        hc, batch, Wp1, bp1, Wp2, bp2, pooledp, N);
    readout_kernel<<<(G + 63) / 64, 256, RO_SMEM_BYTES>>>(
        pooledp, Wr1, br1, Wr2, br2, out, G);
}